// round 5
// baseline (speedup 1.0000x reference)
#include <cuda_runtime.h>
#include <math.h>
#include <stdint.h>

#define BB 16
#define LL1 512
#define LL2 512
#define EMB 300
#define AH 256
#define ATTD 250
#define HID 128
#define ATT_IN 812
#define RNN_IN 1280
#define GATES 512  // 4*HID

// ---------------- scratch (device globals; no allocation allowed) ----------------
__device__ float g_xatt[2 * BB * 512 * ATT_IN];   // x1att rows 0..8191, x2att rows 8192..16383
__device__ float g_r[3 * 16384 * 256];            // per head: [16384][256] (ATTD padded)
__device__ float g_scores[BB * LL1 * LL2];
__device__ float g_x1cat[BB * LL1 * RNN_IN];
__device__ float g_gin[LL1 * BB * 1024];          // [l*16+b][dir*512 + gate]
__device__ float g_Wih[1024 * RNN_IN];            // rows 0..511 fwd, 512..1023 bwd
__device__ float g_bih[1024];

// ---------------- concat builders ----------------
__global__ void build_xatt(const float* __restrict__ w1, const float* __restrict__ a10,
                           const float* __restrict__ a11, const float* __restrict__ w2,
                           const float* __restrict__ a20, const float* __restrict__ a21) {
    long idx = (long)blockIdx.x * blockDim.x + threadIdx.x;
    if (idx >= (long)2 * BB * 512 * ATT_IN) return;
    int c = (int)(idx % ATT_IN);
    long row = idx / ATT_IN;
    const float* w = w1; const float* a0 = a10; const float* a1 = a11;
    long r = row;
    if (row >= (long)BB * 512) { w = w2; a0 = a20; a1 = a21; r = row - BB * 512; }
    float v;
    if (c < EMB) v = w[r * EMB + c];
    else if (c < EMB + AH) v = a0[r * AH + (c - EMB)];
    else v = a1[r * AH + (c - EMB - AH)];
    g_xatt[idx] = v;
}

__global__ void build_x1cat_head(const float* __restrict__ a0, const float* __restrict__ a1) {
    int idx = blockIdx.x * blockDim.x + threadIdx.x;
    if (idx >= BB * LL1 * 512) return;
    int c = idx % 512;
    int r = idx / 512;
    float v = (c < 256) ? a0[r * 256 + c] : a1[r * 256 + (c - 256)];
    g_x1cat[(long)r * RNN_IN + c] = v;
}

__global__ void build_wih(const float* __restrict__ Wf, const float* __restrict__ Wb,
                          const float* __restrict__ bf, const float* __restrict__ bb) {
    int idx = blockIdx.x * blockDim.x + threadIdx.x;
    if (idx < 1024) g_bih[idx] = (idx < 512) ? bf[idx] : bb[idx - 512];
    if (idx >= 1024 * RNN_IN) return;
    int row = idx / RNN_IN;
    int col = idx % RNN_IN;
    g_Wih[idx] = (row < 512) ? Wf[row * RNN_IN + col] : Wb[(row - 512) * RNN_IN + col];
}

// ---------------- tf32 helpers ----------------
__device__ __forceinline__ float cvt_tf32(float x) {
    uint32_t u;
    asm("cvt.rna.tf32.f32 %0, %1;" : "=r"(u) : "f"(x));
    return __uint_as_float(u);
}

__device__ __forceinline__ void mma_tf32(float* d, const uint32_t* a, const uint32_t* b) {
    asm volatile(
        "mma.sync.aligned.m16n8k8.row.col.f32.tf32.tf32.f32 "
        "{%0,%1,%2,%3}, {%4,%5,%6,%7}, {%8,%9}, {%0,%1,%2,%3};"
        : "+f"(d[0]), "+f"(d[1]), "+f"(d[2]), "+f"(d[3])
        : "r"(a[0]), "r"(a[1]), "r"(a[2]), "r"(a[3]), "r"(b[0]), "r"(b[1]));
}

// ---------- 3xTF32 tensor-core GEMM: 128x128 block, 8 warps (2m x 4n) ----------
// Fragment-packed smem: A frag idx ((r*2+kb)*32+lane)*4+e, B frag ((nt*2+kb)*32+lane)*2+e.
// acc += Ab*Bb + Ab*Bs + As*Bb.
__global__ void __launch_bounds__(256, 2)
gemm_tc(const float* __restrict__ A, int lda, long sA,
        const float* __restrict__ Bm, int ldb, long sB, int transB,
        float* __restrict__ C, int ldc, long sC,
        int M, int N, int K,
        const float* __restrict__ bias,
        const float* __restrict__ vscale, int vzstride, int vstart,
        int doRelu, int permuteOut) {
    __shared__ float AfB[2048];
    __shared__ float AfS[2048];
    __shared__ float BfB[2048];
    __shared__ float BfS[2048];

    int z = blockIdx.z;
    A += z * sA;
    Bm += z * sB;
    C += z * sC;

    int m0 = blockIdx.y * 128;
    int n0 = blockIdx.x * 128;
    int tid = threadIdx.x;
    int wid = tid >> 5;
    int lane = tid & 31;
    int g = lane >> 2;
    int tg = lane & 3;
    int warp_m = wid & 1;
    int warp_n = wid >> 1;

    float acc[4][4][4];
#pragma unroll
    for (int i = 0; i < 4; i++)
#pragma unroll
        for (int j = 0; j < 4; j++)
#pragma unroll
            for (int q = 0; q < 4; q++) acc[i][j][q] = 0.f;

    // staging indices
    int arow = tid >> 1;           // 0..127
    int akh = (tid & 1) * 8;       // 0 or 8
    int bk = tid >> 4;             // non-trans: k 0..15
    int bn4 = (tid & 15) * 8;      // non-trans: n 0..120

    // fragment-store bases
    int r_m = arow >> 4;
    int subm = arow & 15;
    int gA = subm & 7;
    int ehi = subm >> 3;
    int kbA = akh >> 3;
    int baseA = ((r_m * 2 + kbA) * 32 + gA * 4) * 4 + ehi;
    // transB B staging base
    int ntB = arow >> 3;
    int gB = arow & 7;
    int baseB = ((ntB * 2 + kbA) * 32 + gB * 4) * 2;
    // non-trans B staging
    int kkB = bk & 7;
    int kbB = bk >> 3;
    int tgB = kkB & 3;
    int ekB = kkB >> 2;

    float ar[8], br[8];

    // ---- prologue load (k0 = 0) ----
    {
        const float* ap = A + (long)(m0 + arow) * lda + akh;
        if (16 <= K) {
            float4 v0 = *(const float4*)ap;
            float4 v1 = *(const float4*)(ap + 4);
            ar[0] = v0.x; ar[1] = v0.y; ar[2] = v0.z; ar[3] = v0.w;
            ar[4] = v1.x; ar[5] = v1.y; ar[6] = v1.z; ar[7] = v1.w;
        } else {
#pragma unroll
            for (int j = 0; j < 8; j++) ar[j] = (akh + j < K) ? ap[j] : 0.f;
        }
        if (transB) {
            bool nok = (n0 + arow) < N;
            const float* bp = Bm + (long)(n0 + arow) * ldb + akh;
            if (nok && 16 <= K) {
                float4 v0 = *(const float4*)bp;
                float4 v1 = *(const float4*)(bp + 4);
                br[0] = v0.x; br[1] = v0.y; br[2] = v0.z; br[3] = v0.w;
                br[4] = v1.x; br[5] = v1.y; br[6] = v1.z; br[7] = v1.w;
            } else {
#pragma unroll
                for (int j = 0; j < 8; j++) br[j] = (nok && akh + j < K) ? bp[j] : 0.f;
            }
        } else {
            bool kok = bk < K;
            const float* bp = Bm + (long)bk * ldb + n0 + bn4;
            if (kok && n0 + bn4 + 8 <= N) {
                float4 v0 = *(const float4*)bp;
                float4 v1 = *(const float4*)(bp + 4);
                br[0] = v0.x; br[1] = v0.y; br[2] = v0.z; br[3] = v0.w;
                br[4] = v1.x; br[5] = v1.y; br[6] = v1.z; br[7] = v1.w;
            } else {
#pragma unroll
                for (int j = 0; j < 8; j++) br[j] = (kok && n0 + bn4 + j < N) ? bp[j] : 0.f;
            }
        }
    }

    for (int k0 = 0; k0 < K; k0 += 16) {
        // ---- split + store to fragment smem ----
#pragma unroll
        for (int j = 0; j < 8; j++) {
            float big = cvt_tf32(ar[j]);
            int off = baseA + (j & 3) * 4 + (j >> 2) * 2;
            AfB[off] = big;
            AfS[off] = cvt_tf32(ar[j] - big);
        }
        if (transB) {
#pragma unroll
            for (int j = 0; j < 8; j++) {
                float big = cvt_tf32(br[j]);
                int off = baseB + (j & 3) * 2 + (j >> 2);
                BfB[off] = big;
                BfS[off] = cvt_tf32(br[j] - big);
            }
        } else {
#pragma unroll
            for (int j = 0; j < 8; j++) {
                int n = bn4 + j;
                int off = (((n >> 3) * 2 + kbB) * 32 + (n & 7) * 4 + tgB) * 2 + ekB;
                float big = cvt_tf32(br[j]);
                BfB[off] = big;
                BfS[off] = cvt_tf32(br[j] - big);
            }
        }
        __syncthreads();

        // ---- prefetch next tile into regs ----
        int kn = k0 + 16;
        if (kn < K) {
            const float* ap = A + (long)(m0 + arow) * lda + kn + akh;
            if (kn + 16 <= K) {
                float4 v0 = *(const float4*)ap;
                float4 v1 = *(const float4*)(ap + 4);
                ar[0] = v0.x; ar[1] = v0.y; ar[2] = v0.z; ar[3] = v0.w;
                ar[4] = v1.x; ar[5] = v1.y; ar[6] = v1.z; ar[7] = v1.w;
            } else {
#pragma unroll
                for (int j = 0; j < 8; j++) ar[j] = (kn + akh + j < K) ? ap[j] : 0.f;
            }
            if (transB) {
                bool nok = (n0 + arow) < N;
                const float* bp = Bm + (long)(n0 + arow) * ldb + kn + akh;
                if (nok && kn + 16 <= K) {
                    float4 v0 = *(const float4*)bp;
                    float4 v1 = *(const float4*)(bp + 4);
                    br[0] = v0.x; br[1] = v0.y; br[2] = v0.z; br[3] = v0.w;
                    br[4] = v1.x; br[5] = v1.y; br[6] = v1.z; br[7] = v1.w;
                } else {
#pragma unroll
                    for (int j = 0; j < 8; j++) br[j] = (nok && kn + akh + j < K) ? bp[j] : 0.f;
                }
            } else {
                bool kok = kn + bk < K;
                const float* bp = Bm + (long)(kn + bk) * ldb + n0 + bn4;
                if (kok && n0 + bn4 + 8 <= N) {
                    float4 v0 = *(const float4*)bp;
                    float4 v1 = *(const float4*)(bp + 4);
                    br[0] = v0.x; br[1] = v0.y; br[2] = v0.z; br[3] = v0.w;
                    br[4] = v1.x; br[5] = v1.y; br[6] = v1.z; br[7] = v1.w;
                } else {
#pragma unroll
                    for (int j = 0; j < 8; j++) br[j] = (kok && n0 + bn4 + j < N) ? bp[j] : 0.f;
                }
            }
        }

        // ---- MMA over two k8 slices, 3xTF32, wide fragment loads ----
#pragma unroll
        for (int kb = 0; kb < 2; kb++) {
            uint32_t afB[4][4], afS[4][4];
#pragma unroll
            for (int mi = 0; mi < 4; mi++) {
                int r = warp_m * 4 + mi;
                int idx = ((r * 2 + kb) * 32 + lane) * 4;
                float4 vb = *(const float4*)&AfB[idx];
                float4 vs = *(const float4*)&AfS[idx];
                afB[mi][0] = __float_as_uint(vb.x); afB[mi][1] = __float_as_uint(vb.y);
                afB[mi][2] = __float_as_uint(vb.z); afB[mi][3] = __float_as_uint(vb.w);
                afS[mi][0] = __float_as_uint(vs.x); afS[mi][1] = __float_as_uint(vs.y);
                afS[mi][2] = __float_as_uint(vs.z); afS[mi][3] = __float_as_uint(vs.w);
            }
            uint32_t bfB[4][2], bfS[4][2];
#pragma unroll
            for (int nj = 0; nj < 4; nj++) {
                int nt = warp_n * 4 + nj;
                int idx = ((nt * 2 + kb) * 32 + lane) * 2;
                float2 vb = *(const float2*)&BfB[idx];
                float2 vs = *(const float2*)&BfS[idx];
                bfB[nj][0] = __float_as_uint(vb.x); bfB[nj][1] = __float_as_uint(vb.y);
                bfS[nj][0] = __float_as_uint(vs.x); bfS[nj][1] = __float_as_uint(vs.y);
            }
#pragma unroll
            for (int mi = 0; mi < 4; mi++)
#pragma unroll
                for (int nj = 0; nj < 4; nj++) {
                    mma_tf32(acc[mi][nj], afS[mi], bfB[nj]);
                    mma_tf32(acc[mi][nj], afB[mi], bfS[nj]);
                    mma_tf32(acc[mi][nj], afB[mi], bfB[nj]);
                }
        }
        __syncthreads();
    }

    // ---- epilogue ----
    bool applyV = (vscale != nullptr) && (m0 >= vstart);
    const float* vs = vscale + (long)z * vzstride;
#pragma unroll
    for (int mi = 0; mi < 4; mi++) {
        int r0 = m0 + warp_m * 64 + mi * 16 + g;
        int r1 = r0 + 8;
        int o0 = permuteOut ? ((r0 & 511) * 16 + (r0 >> 9)) : r0;
        int o1 = permuteOut ? ((r1 & 511) * 16 + (r1 >> 9)) : r1;
        float* c0p = C + (long)o0 * ldc;
        float* c1p = C + (long)o1 * ldc;
#pragma unroll
        for (int nj = 0; nj < 4; nj++) {
            int col = n0 + warp_n * 32 + nj * 8 + 2 * tg;
            if (col >= N) continue;   // N even -> pair-guard safe
            float v0 = acc[mi][nj][0], v1 = acc[mi][nj][1];
            float v2 = acc[mi][nj][2], v3 = acc[mi][nj][3];
            if (bias) {
                float b0 = bias[col], b1 = bias[col + 1];
                v0 += b0; v1 += b1; v2 += b0; v3 += b1;
            }
            if (doRelu) {
                v0 = fmaxf(v0, 0.f); v1 = fmaxf(v1, 0.f);
                v2 = fmaxf(v2, 0.f); v3 = fmaxf(v3, 0.f);
            }
            if (applyV) {
                float s0 = vs[col], s1 = vs[col + 1];
                v0 *= s0; v1 *= s1; v2 *= s0; v3 *= s1;
            }
            *(float2*)(c0p + col) = make_float2(v0, v1);
            *(float2*)(c1p + col) = make_float2(v2, v3);
        }
    }
}

// ---------------- masked softmax over rows of g_scores ----------------
__global__ void softmax_rows(const unsigned char* __restrict__ mask) {
    int r = blockIdx.x;          // b*512 + l
    int b = r >> 9;
    float* row = g_scores + (long)r * LL2;
    __shared__ float red[256];
    int t = threadIdx.x;

    float v0 = row[t];
    float v1 = row[t + 256];
    if (mask[b * LL2 + t]) v0 = -3.402823466e38f;
    if (mask[b * LL2 + t + 256]) v1 = -3.402823466e38f;

    float mx = fmaxf(v0, v1);
    red[t] = mx;
    __syncthreads();
    for (int s = 128; s > 0; s >>= 1) {
        if (t < s) red[t] = fmaxf(red[t], red[t + s]);
        __syncthreads();
    }
    mx = red[0];
    __syncthreads();

    v0 = __expf(v0 - mx);
    v1 = __expf(v1 - mx);
    red[t] = v0 + v1;
    __syncthreads();
    for (int s = 128; s > 0; s >>= 1) {
        if (t < s) red[t] += red[t + s];
        __syncthreads();
    }
    float inv = 1.f / red[0];
    row[t] = v0 * inv;
    row[t + 256] = v1 * inv;
}

// ---------------- BiLSTM recurrence ----------------
__global__ void __launch_bounds__(512, 1)
lstm_kernel(const float* __restrict__ WhhF, const float* __restrict__ WhhB,
            float* __restrict__ out) {
    extern __shared__ float sm[];
    float4* sW4 = (float4*)sm;              // [16][512] float4 = 128KB
    float* h_sh = sm + 16 * 512 * 4;        // [128]
    float* z_sh = h_sh + 128;               // [512]

    int b = blockIdx.x;
    int dir = blockIdx.y;
    const float* Whh = dir ? WhhB : WhhF;
    int j = threadIdx.x;

    float wreg[64];
#pragma unroll
    for (int k = 0; k < 64; k++) wreg[k] = Whh[j * HID + k];
#pragma unroll
    for (int k4 = 0; k4 < 16; k4++) {
        float4 w;
        w.x = Whh[j * HID + 64 + k4 * 4 + 0];
        w.y = Whh[j * HID + 64 + k4 * 4 + 1];
        w.z = Whh[j * HID + 64 + k4 * 4 + 2];
        w.w = Whh[j * HID + 64 + k4 * 4 + 3];
        sW4[k4 * 512 + j] = w;
    }
    if (j < HID) h_sh[j] = 0.f;
    float c = 0.f;
    __syncthreads();

    int gofs = dir * 512 + j;
    int l0 = dir ? (LL1 - 1) : 0;
    float gcur = g_gin[((long)l0 * BB + b) * 1024 + gofs];

    for (int s = 0; s < LL1; s++) {
        int l = dir ? (LL1 - 1 - s) : s;
        float gnext = 0.f;
        if (s + 1 < LL1) {
            int ln = dir ? (LL1 - 2 - s) : (s + 1);
            gnext = g_gin[((long)ln * BB + b) * 1024 + gofs];
        }

        float acc = gcur;
#pragma unroll
        for (int k = 0; k < 64; k += 4) {
            float4 hh = *(const float4*)&h_sh[k];
            acc += hh.x * wreg[k] + hh.y * wreg[k + 1] + hh.z * wreg[k + 2] + hh.w * wreg[k + 3];
        }
#pragma unroll
        for (int k4 = 0; k4 < 16; k4++) {
            float4 hh = *(const float4*)&h_sh[64 + k4 * 4];
            float4 w = sW4[k4 * 512 + j];
            acc += hh.x * w.x + hh.y * w.y + hh.z * w.z + hh.w * w.w;
        }
        z_sh[j] = acc;
        __syncthreads();
        if (j < HID) {
            float zi = z_sh[j], zf = z_sh[j + 128], zg = z_sh[j + 256], zo = z_sh[j + 384];
            float ii = 1.f / (1.f + __expf(-zi));
            float ff = 1.f / (1.f + __expf(-zf));
            float gg = tanhf(zg);
            float oo = 1.f / (1.f + __expf(-zo));
            c = ff * c + ii * gg;
            float h = oo * tanhf(c);
            h_sh[j] = h;
            out[((long)b * LL1 + l) * 256 + dir * HID + j] = h;
        }
        gcur = gnext;
        __syncthreads();
    }
}

// ---------------- launcher ----------------
extern "C" void kernel_launch(void* const* d_in, const int* in_sizes, int n_in,
                              void* d_out, int out_size) {
    const float* x1_word = (const float*)d_in[0];
    const float* x1_a0   = (const float*)d_in[1];
    const float* x1_a1   = (const float*)d_in[2];
    const float* x2_word = (const float*)d_in[3];
    const float* x2_a0   = (const float*)d_in[4];
    const float* x2_a1   = (const float*)d_in[5];
    const float* x2_a2   = (const float*)d_in[6];
    const unsigned char* x2_mask = (const unsigned char*)d_in[8];
    const float* W_attn  = (const float*)d_in[9];
    const float* v_attn  = (const float*)d_in[10];
    const float* Wih_f   = (const float*)d_in[11];
    const float* Whh_f   = (const float*)d_in[12];
    const float* b_f     = (const float*)d_in[13];
    const float* Wih_b   = (const float*)d_in[14];
    const float* Whh_b   = (const float*)d_in[15];
    const float* b_b     = (const float*)d_in[16];
    float* out = (float*)d_out;

    float *xatt, *rbuf, *scores, *x1cat, *wih, *bih;
    cudaGetSymbolAddress((void**)&xatt, g_xatt);
    cudaGetSymbolAddress((void**)&rbuf, g_r);
    cudaGetSymbolAddress((void**)&scores, g_scores);
    cudaGetSymbolAddress((void**)&x1cat, g_x1cat);
    cudaGetSymbolAddress((void**)&wih, g_Wih);
    cudaGetSymbolAddress((void**)&bih, g_bih);
    float* ginbuf;
    cudaGetSymbolAddress((void**)&ginbuf, g_gin);

    // concat inputs
    {
        long n1 = (long)2 * BB * 512 * ATT_IN;
        build_xatt<<<(int)((n1 + 255) / 256), 256>>>(x1_word, x1_a0, x1_a1,
                                                     x2_word, x2_a0, x2_a1);
        int n3 = BB * LL1 * 512;
        build_x1cat_head<<<(n3 + 255) / 256, 256>>>(x1_a0, x1_a1);
        int n4 = 1024 * RNN_IN;
        build_wih<<<(n4 + 255) / 256, 256>>>(Wih_f, Wih_b, b_f, b_b);
    }

    // r = relu([x1att; x2att] @ Wi^T), batched over 3 heads; v applied to x2 rows
    gemm_tc<<<dim3(2, 128, 3), 256>>>(xatt, ATT_IN, 0,
                                      W_attn, ATT_IN, (long)ATTD * ATT_IN, 1,
                                      rbuf, 256, (long)16384 * 256,
                                      16384, ATTD, ATT_IN,
                                      nullptr, v_attn, ATTD, 8192, 1, 0);

    const float* x2_list[3] = {x2_a0, x2_a1, x2_a2};
    for (int i = 0; i < 3; i++) {
        const float* r1 = rbuf + (long)i * 16384 * 256;
        const float* r2 = r1 + (long)8192 * 256;

        // scores[b] = r1[b] @ r2[b]^T  batched 16 x [512 x 512], K=250
        gemm_tc<<<dim3(4, 4, 16), 256>>>(r1, 256, (long)512 * 256,
                                         r2, 256, (long)512 * 256, 1,
                                         scores, 512, (long)512 * 512,
                                         LL1, LL2, ATTD,
                                         nullptr, nullptr, 0, 0, 0, 0);
        softmax_rows<<<BB * LL1, 256>>>(x2_mask);
        // piece_i[b] = alpha[b] @ x2_list[i][b] -> x1cat cols [512+256i, +256)
        gemm_tc<<<dim3(2, 4, 16), 256>>>(scores, 512, (long)512 * 512,
                                         x2_list[i], 256, (long)512 * 256, 0,
                                         x1cat + 512 + 256 * i, RNN_IN, (long)512 * RNN_IN,
                                         LL1, AH, LL2,
                                         nullptr, nullptr, 0, 0, 0, 0);
    }

    // g_in (both dirs) = x1cat @ [Wih_f; Wih_b]^T + b, rows permuted to [l*16+b]
    gemm_tc<<<dim3(8, 64, 1), 256>>>(x1cat, RNN_IN, 0, wih, RNN_IN, 0, 1,
                                     ginbuf, 1024, 0, BB * LL1, 1024, RNN_IN,
                                     bih, nullptr, 0, 0, 0, 1);

    // BiLSTM
    size_t smem = (size_t)(16 * 512 * 4 + 128 + 512) * sizeof(float);
    cudaFuncSetAttribute(lstm_kernel, cudaFuncAttributeMaxDynamicSharedMemorySize, (int)smem);
    lstm_kernel<<<dim3(16, 2), 512, smem>>>(Whh_f, Whh_b, out);
}

// round 6
// speedup vs baseline: 1.3452x; 1.3452x over previous
#include <cuda_runtime.h>
#include <math.h>
#include <stdint.h>

#define BB 16
#define LL1 512
#define LL2 512
#define EMB 300
#define AH 256
#define ATTD 250
#define HID 128
#define ATT_IN 812
#define RNN_IN 1280
#define GATES 512  // 4*HID

// ---------------- scratch (device globals; no allocation allowed) ----------------
__device__ float g_xatt[2 * BB * 512 * ATT_IN];   // x1att rows 0..8191, x2att rows 8192..16383
__device__ float g_r[3 * 16384 * 256];            // per head: [16384][256] (ATTD padded)
__device__ float g_scores[BB * LL1 * LL2];
__device__ float g_x1cat[BB * LL1 * RNN_IN];
__device__ float g_gin[LL1 * BB * 1024];          // [l*16+b][dir*512 + gate]
__device__ float g_Wih[1024 * RNN_IN];            // rows 0..511 fwd, 512..1023 bwd
__device__ float g_bih[1024];

// ---------------- concat builders ----------------
__global__ void build_xatt(const float* __restrict__ w1, const float* __restrict__ a10,
                           const float* __restrict__ a11, const float* __restrict__ w2,
                           const float* __restrict__ a20, const float* __restrict__ a21) {
    long idx = (long)blockIdx.x * blockDim.x + threadIdx.x;
    if (idx >= (long)2 * BB * 512 * ATT_IN) return;
    int c = (int)(idx % ATT_IN);
    long row = idx / ATT_IN;
    const float* w = w1; const float* a0 = a10; const float* a1 = a11;
    long r = row;
    if (row >= (long)BB * 512) { w = w2; a0 = a20; a1 = a21; r = row - BB * 512; }
    float v;
    if (c < EMB) v = w[r * EMB + c];
    else if (c < EMB + AH) v = a0[r * AH + (c - EMB)];
    else v = a1[r * AH + (c - EMB - AH)];
    g_xatt[idx] = v;
}

__global__ void build_x1cat_head(const float* __restrict__ a0, const float* __restrict__ a1) {
    int idx = blockIdx.x * blockDim.x + threadIdx.x;
    if (idx >= BB * LL1 * 512) return;
    int c = idx % 512;
    int r = idx / 512;
    float v = (c < 256) ? a0[r * 256 + c] : a1[r * 256 + (c - 256)];
    g_x1cat[(long)r * RNN_IN + c] = v;
}

__global__ void build_wih(const float* __restrict__ Wf, const float* __restrict__ Wb,
                          const float* __restrict__ bf, const float* __restrict__ bb) {
    int idx = blockIdx.x * blockDim.x + threadIdx.x;
    if (idx < 1024) g_bih[idx] = (idx < 512) ? bf[idx] : bb[idx - 512];
    if (idx >= 1024 * RNN_IN) return;
    int row = idx / RNN_IN;
    int col = idx % RNN_IN;
    g_Wih[idx] = (row < 512) ? Wf[row * RNN_IN + col] : Wb[(row - 512) * RNN_IN + col];
}

// ---------------- tf32 helpers ----------------
__device__ __forceinline__ float cvt_tf32(float x) {
    uint32_t u;
    asm("cvt.rna.tf32.f32 %0, %1;" : "=r"(u) : "f"(x));
    return __uint_as_float(u);
}

__device__ __forceinline__ void mma_tf32(float* d, const uint32_t* a, const uint32_t* b) {
    asm volatile(
        "mma.sync.aligned.m16n8k8.row.col.f32.tf32.tf32.f32 "
        "{%0,%1,%2,%3}, {%4,%5,%6,%7}, {%8,%9}, {%0,%1,%2,%3};"
        : "+f"(d[0]), "+f"(d[1]), "+f"(d[2]), "+f"(d[3])
        : "r"(a[0]), "r"(a[1]), "r"(a[2]), "r"(a[3]), "r"(b[0]), "r"(b[1]));
}

// ---------- 3xTF32 tensor-core GEMM: 128x128 block, 8 warps (2m x 4n) ----------
// Fragment-quad staging: thread t stages exactly the frag-float4s / float2s the
// MMA consumes -> STS.128/STS.64 consecutive-address (conflict-free).
// Double-buffered smem, ONE __syncthreads per 16-k tile.
// Per 16-k tile buffer (floats): AfB[2048] AfS[2048] BfB[2048] BfS[2048] = 32KB.
__global__ void __launch_bounds__(256, 2)
gemm_tc(const float* __restrict__ A, int lda, long sA,
        const float* __restrict__ Bm, int ldb, long sB, int transB,
        float* __restrict__ C, int ldc, long sC,
        int M, int N, int K,
        const float* __restrict__ bias,
        const float* __restrict__ vscale, int vzstride, int vstart,
        int doRelu, int permuteOut) {
    extern __shared__ float sm[];

    int z = blockIdx.z;
    A += z * sA;
    Bm += z * sB;
    C += z * sC;

    int m0 = blockIdx.y * 128;
    int n0 = blockIdx.x * 128;
    int tid = threadIdx.x;
    int wid = tid >> 5;
    int lane = tid & 31;
    int g = lane >> 2;
    int tg = lane & 3;
    int warp_m = wid & 1;
    int warp_n = wid >> 1;

    float acc[4][4][4];
#pragma unroll
    for (int i = 0; i < 4; i++)
#pragma unroll
        for (int j = 0; j < 4; j++)
#pragma unroll
            for (int q = 0; q < 4; q++) acc[i][j][q] = 0.f;

    // ---- staging ownership: quads/pairs in fragment order ----
    // A quad q (0..511): mt=q>>6 (m-16-tile), kb=(q>>5)&1, l=q&31 (mma lane)
    //   values: A[mt*16+gl][kb*8+tl], A[+8][..], A[..][+4], A[+8][+4]
    int rowA[2], kofA[2];
#pragma unroll
    for (int i = 0; i < 2; i++) {
        int q = tid + 256 * i;
        int ql = q & 31;
        rowA[i] = m0 + (q >> 6) * 16 + (ql >> 2);
        kofA[i] = ((q >> 5) & 1) * 8 + (ql & 3);
    }
    // B pair p (0..1023): nt=p>>6 (n-8-tile), kb=(p>>5)&1, l=p&31
    //   values: B'[kb*8+tl][nt*8+gl], B'[kb*8+tl+4][same n]
    int nBr[4], kofB[4];
#pragma unroll
    for (int i = 0; i < 4; i++) {
        int p = tid + 256 * i;
        int pl = p & 31;
        nBr[i] = n0 + (p >> 6) * 8 + (pl >> 2);
        kofB[i] = ((p >> 5) & 1) * 8 + (pl & 3);
    }

    float av[2][4], bv[4][2];

    // ---- prologue load (k0 = 0) ----
#pragma unroll
    for (int i = 0; i < 2; i++) {
        const float* ap = A + (long)rowA[i] * lda;
        int c0 = kofA[i], c1 = kofA[i] + 4;
        av[i][0] = (c0 < K) ? ap[c0] : 0.f;
        av[i][1] = (c0 < K) ? ap[8 * lda + c0] : 0.f;
        av[i][2] = (c1 < K) ? ap[c1] : 0.f;
        av[i][3] = (c1 < K) ? ap[8 * lda + c1] : 0.f;
    }
    if (transB) {
#pragma unroll
        for (int i = 0; i < 4; i++) {
            bool nok = nBr[i] < N;
            const float* bp = Bm + (long)nBr[i] * ldb;
            int c0 = kofB[i], c1 = kofB[i] + 4;
            bv[i][0] = (nok && c0 < K) ? bp[c0] : 0.f;
            bv[i][1] = (nok && c1 < K) ? bp[c1] : 0.f;
        }
    } else {
#pragma unroll
        for (int i = 0; i < 4; i++) {
            bool nok = nBr[i] < N;
            int c0 = kofB[i], c1 = kofB[i] + 4;
            bv[i][0] = (nok && c0 < K) ? Bm[(long)c0 * ldb + nBr[i]] : 0.f;
            bv[i][1] = (nok && c1 < K) ? Bm[(long)c1 * ldb + nBr[i]] : 0.f;
        }
    }

    int nk = (K + 15) >> 4;
    for (int it = 0; it < nk; it++) {
        int k0 = it << 4;
        float* buf = sm + (it & 1) * 8192;
        float* AfB = buf;
        float* AfS = buf + 2048;
        float* BfB = buf + 4096;
        float* BfS = buf + 6144;

        // ---- split + conflict-free wide stores ----
#pragma unroll
        for (int i = 0; i < 2; i++) {
            int q = tid + 256 * i;
            float b0 = cvt_tf32(av[i][0]), b1 = cvt_tf32(av[i][1]);
            float b2 = cvt_tf32(av[i][2]), b3 = cvt_tf32(av[i][3]);
            *(float4*)&AfB[q * 4] = make_float4(b0, b1, b2, b3);
            *(float4*)&AfS[q * 4] = make_float4(cvt_tf32(av[i][0] - b0), cvt_tf32(av[i][1] - b1),
                                                cvt_tf32(av[i][2] - b2), cvt_tf32(av[i][3] - b3));
        }
#pragma unroll
        for (int i = 0; i < 4; i++) {
            int p = tid + 256 * i;
            float b0 = cvt_tf32(bv[i][0]), b1 = cvt_tf32(bv[i][1]);
            *(float2*)&BfB[p * 2] = make_float2(b0, b1);
            *(float2*)&BfS[p * 2] = make_float2(cvt_tf32(bv[i][0] - b0), cvt_tf32(bv[i][1] - b1));
        }

        // ---- prefetch next k-tile into regs (overlaps sync + MMA) ----
        int kn = k0 + 16;
        if (kn < K) {
#pragma unroll
            for (int i = 0; i < 2; i++) {
                const float* ap = A + (long)rowA[i] * lda + kn;
                int c0 = kn + kofA[i], c1 = c0 + 4;
                av[i][0] = (c0 < K) ? ap[kofA[i]] : 0.f;
                av[i][1] = (c0 < K) ? ap[8 * lda + kofA[i]] : 0.f;
                av[i][2] = (c1 < K) ? ap[kofA[i] + 4] : 0.f;
                av[i][3] = (c1 < K) ? ap[8 * lda + kofA[i] + 4] : 0.f;
            }
            if (transB) {
#pragma unroll
                for (int i = 0; i < 4; i++) {
                    bool nok = nBr[i] < N;
                    const float* bp = Bm + (long)nBr[i] * ldb + kn;
                    int c0 = kn + kofB[i], c1 = c0 + 4;
                    bv[i][0] = (nok && c0 < K) ? bp[kofB[i]] : 0.f;
                    bv[i][1] = (nok && c1 < K) ? bp[kofB[i] + 4] : 0.f;
                }
            } else {
#pragma unroll
                for (int i = 0; i < 4; i++) {
                    bool nok = nBr[i] < N;
                    int c0 = kn + kofB[i], c1 = c0 + 4;
                    bv[i][0] = (nok && c0 < K) ? Bm[(long)c0 * ldb + nBr[i]] : 0.f;
                    bv[i][1] = (nok && c1 < K) ? Bm[(long)c1 * ldb + nBr[i]] : 0.f;
                }
            }
        }

        __syncthreads();

        // ---- MMA over two k8 slices, 3xTF32, wide fragment loads ----
#pragma unroll
        for (int kb = 0; kb < 2; kb++) {
            uint32_t afB[4][4], afS[4][4];
#pragma unroll
            for (int mi = 0; mi < 4; mi++) {
                int r = warp_m * 4 + mi;
                int idx = ((r * 2 + kb) * 32 + lane) * 4;
                float4 vb = *(const float4*)&AfB[idx];
                float4 vs = *(const float4*)&AfS[idx];
                afB[mi][0] = __float_as_uint(vb.x); afB[mi][1] = __float_as_uint(vb.y);
                afB[mi][2] = __float_as_uint(vb.z); afB[mi][3] = __float_as_uint(vb.w);
                afS[mi][0] = __float_as_uint(vs.x); afS[mi][1] = __float_as_uint(vs.y);
                afS[mi][2] = __float_as_uint(vs.z); afS[mi][3] = __float_as_uint(vs.w);
            }
            uint32_t bfB[4][2], bfS[4][2];
#pragma unroll
            for (int nj = 0; nj < 4; nj++) {
                int nt = warp_n * 4 + nj;
                int idx = ((nt * 2 + kb) * 32 + lane) * 2;
                float2 vb = *(const float2*)&BfB[idx];
                float2 vs = *(const float2*)&BfS[idx];
                bfB[nj][0] = __float_as_uint(vb.x); bfB[nj][1] = __float_as_uint(vb.y);
                bfS[nj][0] = __float_as_uint(vs.x); bfS[nj][1] = __float_as_uint(vs.y);
            }
#pragma unroll
            for (int mi = 0; mi < 4; mi++)
#pragma unroll
                for (int nj = 0; nj < 4; nj++) {
                    mma_tf32(acc[mi][nj], afS[mi], bfB[nj]);
                    mma_tf32(acc[mi][nj], afB[mi], bfS[nj]);
                    mma_tf32(acc[mi][nj], afB[mi], bfB[nj]);
                }
        }
        // no second sync: ping-pong buffer + the next iteration's sync protect reuse
    }

    // ---- epilogue ----
    bool applyV = (vscale != nullptr) && (m0 >= vstart);
    const float* vs = vscale + (long)z * vzstride;
#pragma unroll
    for (int mi = 0; mi < 4; mi++) {
        int r0 = m0 + warp_m * 64 + mi * 16 + g;
        int r1 = r0 + 8;
        int o0 = permuteOut ? ((r0 & 511) * 16 + (r0 >> 9)) : r0;
        int o1 = permuteOut ? ((r1 & 511) * 16 + (r1 >> 9)) : r1;
        float* c0p = C + (long)o0 * ldc;
        float* c1p = C + (long)o1 * ldc;
#pragma unroll
        for (int nj = 0; nj < 4; nj++) {
            int col = n0 + warp_n * 32 + nj * 8 + 2 * tg;
            if (col >= N) continue;   // N even -> pair-guard safe
            float v0 = acc[mi][nj][0], v1 = acc[mi][nj][1];
            float v2 = acc[mi][nj][2], v3 = acc[mi][nj][3];
            if (bias) {
                float b0 = bias[col], b1 = bias[col + 1];
                v0 += b0; v1 += b1; v2 += b0; v3 += b1;
            }
            if (doRelu) {
                v0 = fmaxf(v0, 0.f); v1 = fmaxf(v1, 0.f);
                v2 = fmaxf(v2, 0.f); v3 = fmaxf(v3, 0.f);
            }
            if (applyV) {
                float s0 = vs[col], s1 = vs[col + 1];
                v0 *= s0; v1 *= s1; v2 *= s0; v3 *= s1;
            }
            *(float2*)(c0p + col) = make_float2(v0, v1);
            *(float2*)(c1p + col) = make_float2(v2, v3);
        }
    }
}

// ---------------- masked softmax over rows of g_scores ----------------
__global__ void softmax_rows(const unsigned char* __restrict__ mask) {
    int r = blockIdx.x;          // b*512 + l
    int b = r >> 9;
    float* row = g_scores + (long)r * LL2;
    __shared__ float red[256];
    int t = threadIdx.x;

    float v0 = row[t];
    float v1 = row[t + 256];
    if (mask[b * LL2 + t]) v0 = -3.402823466e38f;
    if (mask[b * LL2 + t + 256]) v1 = -3.402823466e38f;

    float mx = fmaxf(v0, v1);
    red[t] = mx;
    __syncthreads();
    for (int s = 128; s > 0; s >>= 1) {
        if (t < s) red[t] = fmaxf(red[t], red[t + s]);
        __syncthreads();
    }
    mx = red[0];
    __syncthreads();

    v0 = __expf(v0 - mx);
    v1 = __expf(v1 - mx);
    red[t] = v0 + v1;
    __syncthreads();
    for (int s = 128; s > 0; s >>= 1) {
        if (t < s) red[t] += red[t + s];
        __syncthreads();
    }
    float inv = 1.f / red[0];
    row[t] = v0 * inv;
    row[t + 256] = v1 * inv;
}

// ---------------- BiLSTM recurrence ----------------
__global__ void __launch_bounds__(512, 1)
lstm_kernel(const float* __restrict__ WhhF, const float* __restrict__ WhhB,
            float* __restrict__ out) {
    extern __shared__ float sm[];
    float4* sW4 = (float4*)sm;              // [16][512] float4 = 128KB
    float* h_sh = sm + 16 * 512 * 4;        // [128]
    float* z_sh = h_sh + 128;               // [512]

    int b = blockIdx.x;
    int dir = blockIdx.y;
    const float* Whh = dir ? WhhB : WhhF;
    int j = threadIdx.x;

    float wreg[64];
#pragma unroll
    for (int k = 0; k < 64; k++) wreg[k] = Whh[j * HID + k];
#pragma unroll
    for (int k4 = 0; k4 < 16; k4++) {
        float4 w;
        w.x = Whh[j * HID + 64 + k4 * 4 + 0];
        w.y = Whh[j * HID + 64 + k4 * 4 + 1];
        w.z = Whh[j * HID + 64 + k4 * 4 + 2];
        w.w = Whh[j * HID + 64 + k4 * 4 + 3];
        sW4[k4 * 512 + j] = w;
    }
    if (j < HID) h_sh[j] = 0.f;
    float c = 0.f;
    __syncthreads();

    int gofs = dir * 512 + j;
    int l0 = dir ? (LL1 - 1) : 0;
    float gcur = g_gin[((long)l0 * BB + b) * 1024 + gofs];

    for (int s = 0; s < LL1; s++) {
        int l = dir ? (LL1 - 1 - s) : s;
        float gnext = 0.f;
        if (s + 1 < LL1) {
            int ln = dir ? (LL1 - 2 - s) : (s + 1);
            gnext = g_gin[((long)ln * BB + b) * 1024 + gofs];
        }

        float acc = gcur;
#pragma unroll
        for (int k = 0; k < 64; k += 4) {
            float4 hh = *(const float4*)&h_sh[k];
            acc += hh.x * wreg[k] + hh.y * wreg[k + 1] + hh.z * wreg[k + 2] + hh.w * wreg[k + 3];
        }
#pragma unroll
        for (int k4 = 0; k4 < 16; k4++) {
            float4 hh = *(const float4*)&h_sh[64 + k4 * 4];
            float4 w = sW4[k4 * 512 + j];
            acc += hh.x * w.x + hh.y * w.y + hh.z * w.z + hh.w * w.w;
        }
        z_sh[j] = acc;
        __syncthreads();
        if (j < HID) {
            float zi = z_sh[j], zf = z_sh[j + 128], zg = z_sh[j + 256], zo = z_sh[j + 384];
            float ii = 1.f / (1.f + __expf(-zi));
            float ff = 1.f / (1.f + __expf(-zf));
            float gg = tanhf(zg);
            float oo = 1.f / (1.f + __expf(-zo));
            c = ff * c + ii * gg;
            float h = oo * tanhf(c);
            h_sh[j] = h;
            out[((long)b * LL1 + l) * 256 + dir * HID + j] = h;
        }
        gcur = gnext;
        __syncthreads();
    }
}

// ---------------- launcher ----------------
extern "C" void kernel_launch(void* const* d_in, const int* in_sizes, int n_in,
                              void* d_out, int out_size) {
    const float* x1_word = (const float*)d_in[0];
    const float* x1_a0   = (const float*)d_in[1];
    const float* x1_a1   = (const float*)d_in[2];
    const float* x2_word = (const float*)d_in[3];
    const float* x2_a0   = (const float*)d_in[4];
    const float* x2_a1   = (const float*)d_in[5];
    const float* x2_a2   = (const float*)d_in[6];
    const unsigned char* x2_mask = (const unsigned char*)d_in[8];
    const float* W_attn  = (const float*)d_in[9];
    const float* v_attn  = (const float*)d_in[10];
    const float* Wih_f   = (const float*)d_in[11];
    const float* Whh_f   = (const float*)d_in[12];
    const float* b_f     = (const float*)d_in[13];
    const float* Wih_b   = (const float*)d_in[14];
    const float* Whh_b   = (const float*)d_in[15];
    const float* b_b     = (const float*)d_in[16];
    float* out = (float*)d_out;

    float *xatt, *rbuf, *scores, *x1cat, *wih, *bih, *ginbuf;
    cudaGetSymbolAddress((void**)&xatt, g_xatt);
    cudaGetSymbolAddress((void**)&rbuf, g_r);
    cudaGetSymbolAddress((void**)&scores, g_scores);
    cudaGetSymbolAddress((void**)&x1cat, g_x1cat);
    cudaGetSymbolAddress((void**)&wih, g_Wih);
    cudaGetSymbolAddress((void**)&bih, g_bih);
    cudaGetSymbolAddress((void**)&ginbuf, g_gin);

    const int GEMM_SMEM = 2 * 8192 * 4;  // 64 KB (double-buffered frag tiles)
    cudaFuncSetAttribute(gemm_tc, cudaFuncAttributeMaxDynamicSharedMemorySize, GEMM_SMEM);

    // concat inputs
    {
        long n1 = (long)2 * BB * 512 * ATT_IN;
        build_xatt<<<(int)((n1 + 255) / 256), 256>>>(x1_word, x1_a0, x1_a1,
                                                     x2_word, x2_a0, x2_a1);
        int n3 = BB * LL1 * 512;
        build_x1cat_head<<<(n3 + 255) / 256, 256>>>(x1_a0, x1_a1);
        int n4 = 1024 * RNN_IN;
        build_wih<<<(n4 + 255) / 256, 256>>>(Wih_f, Wih_b, b_f, b_b);
    }

    // r = relu([x1att; x2att] @ Wi^T), batched over 3 heads; v applied to x2 rows
    gemm_tc<<<dim3(2, 128, 3), 256, GEMM_SMEM>>>(xatt, ATT_IN, 0,
                                      W_attn, ATT_IN, (long)ATTD * ATT_IN, 1,
                                      rbuf, 256, (long)16384 * 256,
                                      16384, ATTD, ATT_IN,
                                      nullptr, v_attn, ATTD, 8192, 1, 0);

    const float* x2_list[3] = {x2_a0, x2_a1, x2_a2};
    for (int i = 0; i < 3; i++) {
        const float* r1 = rbuf + (long)i * 16384 * 256;
        const float* r2 = r1 + (long)8192 * 256;

        // scores[b] = r1[b] @ r2[b]^T  batched 16 x [512 x 512], K=250
        gemm_tc<<<dim3(4, 4, 16), 256, GEMM_SMEM>>>(r1, 256, (long)512 * 256,
                                         r2, 256, (long)512 * 256, 1,
                                         scores, 512, (long)512 * 512,
                                         LL1, LL2, ATTD,
                                         nullptr, nullptr, 0, 0, 0, 0);
        softmax_rows<<<BB * LL1, 256>>>(x2_mask);
        // piece_i[b] = alpha[b] @ x2_list[i][b] -> x1cat cols [512+256i, +256)
        gemm_tc<<<dim3(2, 4, 16), 256, GEMM_SMEM>>>(scores, 512, (long)512 * 512,
                                         x2_list[i], 256, (long)512 * 256, 0,
                                         x1cat + 512 + 256 * i, RNN_IN, (long)512 * RNN_IN,
                                         LL1, AH, LL2,
                                         nullptr, nullptr, 0, 0, 0, 0);
    }

    // g_in (both dirs) = x1cat @ [Wih_f; Wih_b]^T + b, rows permuted to [l*16+b]
    gemm_tc<<<dim3(8, 64, 1), 256, GEMM_SMEM>>>(x1cat, RNN_IN, 0, wih, RNN_IN, 0, 1,
                                     ginbuf, 1024, 0, BB * LL1, 1024, RNN_IN,
                                     bih, nullptr, 0, 0, 0, 1);

    // BiLSTM
    size_t smem = (size_t)(16 * 512 * 4 + 128 + 512) * sizeof(float);
    cudaFuncSetAttribute(lstm_kernel, cudaFuncAttributeMaxDynamicSharedMemorySize, (int)smem);
    lstm_kernel<<<dim3(16, 2), 512, smem>>>(Whh_f, Whh_b, out);
}

// round 7
// speedup vs baseline: 1.3466x; 1.0011x over previous
#include <cuda_runtime.h>
#include <math.h>
#include <stdint.h>

#define BB 16
#define LL1 512
#define LL2 512
#define EMB 300
#define AH 256
#define ATTD 250
#define HID 128
#define ATT_IN 812
#define RNN_IN 1280
#define GATES 512  // 4*HID

// ---------------- scratch (device globals; no allocation allowed) ----------------
__device__ float g_xatt[2 * BB * 512 * ATT_IN];   // x1att rows 0..8191, x2att rows 8192..16383
__device__ float g_r[3 * 16384 * 256];            // per head: [16384][256] (ATTD padded)
__device__ float g_scores[BB * LL1 * LL2];
__device__ float g_x1cat[BB * LL1 * RNN_IN];
__device__ float g_gin[LL1 * BB * 1024];          // [l*16+b][dir*512 + gate]
__device__ float g_Wih[1024 * RNN_IN];            // rows 0..511 fwd, 512..1023 bwd
__device__ float g_bih[1024];

// ---------------- concat builders ----------------
__global__ void build_xatt(const float* __restrict__ w1, const float* __restrict__ a10,
                           const float* __restrict__ a11, const float* __restrict__ w2,
                           const float* __restrict__ a20, const float* __restrict__ a21) {
    long idx = (long)blockIdx.x * blockDim.x + threadIdx.x;
    if (idx >= (long)2 * BB * 512 * ATT_IN) return;
    int c = (int)(idx % ATT_IN);
    long row = idx / ATT_IN;
    const float* w = w1; const float* a0 = a10; const float* a1 = a11;
    long r = row;
    if (row >= (long)BB * 512) { w = w2; a0 = a20; a1 = a21; r = row - BB * 512; }
    float v;
    if (c < EMB) v = w[r * EMB + c];
    else if (c < EMB + AH) v = a0[r * AH + (c - EMB)];
    else v = a1[r * AH + (c - EMB - AH)];
    g_xatt[idx] = v;
}

__global__ void build_x1cat_head(const float* __restrict__ a0, const float* __restrict__ a1) {
    int idx = blockIdx.x * blockDim.x + threadIdx.x;
    if (idx >= BB * LL1 * 512) return;
    int c = idx % 512;
    int r = idx / 512;
    float v = (c < 256) ? a0[r * 256 + c] : a1[r * 256 + (c - 256)];
    g_x1cat[(long)r * RNN_IN + c] = v;
}

__global__ void build_wih(const float* __restrict__ Wf, const float* __restrict__ Wb,
                          const float* __restrict__ bf, const float* __restrict__ bb) {
    int idx = blockIdx.x * blockDim.x + threadIdx.x;
    if (idx < 1024) g_bih[idx] = (idx < 512) ? bf[idx] : bb[idx - 512];
    if (idx >= 1024 * RNN_IN) return;
    int row = idx / RNN_IN;
    int col = idx % RNN_IN;
    g_Wih[idx] = (row < 512) ? Wf[row * RNN_IN + col] : Wb[(row - 512) * RNN_IN + col];
}

// ---------------- tf32 / f32x2 helpers ----------------
__device__ __forceinline__ float cvt_tf32(float x) {
    uint32_t u;
    asm("cvt.rna.tf32.f32 %0, %1;" : "=r"(u) : "f"(x));
    return __uint_as_float(u);
}

__device__ __forceinline__ void mma_tf32(float* d, const uint32_t* a, const uint32_t* b) {
    asm volatile(
        "mma.sync.aligned.m16n8k8.row.col.f32.tf32.tf32.f32 "
        "{%0,%1,%2,%3}, {%4,%5,%6,%7}, {%8,%9}, {%0,%1,%2,%3};"
        : "+f"(d[0]), "+f"(d[1]), "+f"(d[2]), "+f"(d[3])
        : "r"(a[0]), "r"(a[1]), "r"(a[2]), "r"(a[3]), "r"(b[0]), "r"(b[1]));
}

__device__ __forceinline__ unsigned long long fma2_(unsigned long long a,
                                                   unsigned long long b,
                                                   unsigned long long c) {
    unsigned long long d;
    asm("fma.rn.f32x2 %0, %1, %2, %3;" : "=l"(d) : "l"(a), "l"(b), "l"(c));
    return d;
}

// ---------- 3xTF32 tensor-core GEMM: 128x128 block, 8 warps (2m x 4n) ----------
// Fragment-quad staging (conflict-free STS.128/STS.64), double-buffered smem,
// one sync per 16-k tile, persistent load pointers + unguarded steady-state.
__global__ void __launch_bounds__(256, 2)
gemm_tc(const float* __restrict__ A, int lda, long sA,
        const float* __restrict__ Bm, int ldb, long sB, int transB,
        float* __restrict__ C, int ldc, long sC,
        int M, int N, int K,
        const float* __restrict__ bias,
        const float* __restrict__ vscale, int vzstride, int vstart,
        int doRelu, int permuteOut) {
    extern __shared__ float sm[];

    int z = blockIdx.z;
    A += z * sA;
    Bm += z * sB;
    C += z * sC;

    int m0 = blockIdx.y * 128;
    int n0 = blockIdx.x * 128;
    int tid = threadIdx.x;
    int wid = tid >> 5;
    int lane = tid & 31;
    int g = lane >> 2;
    int tg = lane & 3;
    int warp_m = wid & 1;
    int warp_n = wid >> 1;

    float acc[4][4][4];
#pragma unroll
    for (int i = 0; i < 4; i++)
#pragma unroll
        for (int j = 0; j < 4; j++)
#pragma unroll
            for (int q = 0; q < 4; q++) acc[i][j][q] = 0.f;

    // ---- staging ownership (identical layout to the passing R6 kernel) ----
    int rowA[2], kofA[2], sAoff[2];
#pragma unroll
    for (int i = 0; i < 2; i++) {
        int q = tid + 256 * i;
        int ql = q & 31;
        rowA[i] = m0 + (q >> 6) * 16 + (ql >> 2);
        kofA[i] = ((q >> 5) & 1) * 8 + (ql & 3);
        sAoff[i] = q * 4;
    }
    int nBr[4], kofB[4], sBoff[4];
    float nmask[4];
#pragma unroll
    for (int i = 0; i < 4; i++) {
        int p = tid + 256 * i;
        int pl = p & 31;
        nBr[i] = n0 + (p >> 6) * 8 + (pl >> 2);
        kofB[i] = ((p >> 5) & 1) * 8 + (pl & 3);
        sBoff[i] = p * 2;
        nmask[i] = (nBr[i] < N) ? 1.f : 0.f;
    }

    // persistent pointers (clamped rows so steady-state loads are in-bounds)
    const float* aP[2];
#pragma unroll
    for (int i = 0; i < 2; i++) aP[i] = A + (long)rowA[i] * lda + kofA[i];
    const float* bP[4];
    long bAdv = transB ? 16 : (long)16 * ldb;
#pragma unroll
    for (int i = 0; i < 4; i++) {
        int nc = (nBr[i] < N) ? nBr[i] : (N - 1);
        bP[i] = transB ? (Bm + (long)nc * ldb + kofB[i])
                       : (Bm + (long)kofB[i] * ldb + nc);
    }
    int bStride = transB ? 4 : 4 * ldb;   // offset between the two staged B values

    float av[2][4], bv[4][2];

    int fullT = K >> 4;
    int nk = (K + 15) >> 4;

    // ---- prologue load tile 0 (guarded; kofA/kofB < 16) ----
#pragma unroll
    for (int i = 0; i < 2; i++) {
        int c0 = kofA[i], c1 = c0 + 4;
        float v0 = 0.f, v1 = 0.f, v2 = 0.f, v3 = 0.f;
        if (c0 < K) { v0 = aP[i][0]; v1 = aP[i][8 * lda]; }
        if (c1 < K) { v2 = aP[i][4]; v3 = aP[i][8 * lda + 4]; }
        av[i][0] = v0; av[i][1] = v1; av[i][2] = v2; av[i][3] = v3;
    }
#pragma unroll
    for (int i = 0; i < 4; i++) {
        int c0 = kofB[i], c1 = c0 + 4;
        float v0 = 0.f, v1 = 0.f;
        if (c0 < K) v0 = bP[i][0];
        if (c1 < K) v1 = bP[i][bStride];
        bv[i][0] = v0 * nmask[i];
        bv[i][1] = v1 * nmask[i];
    }

    for (int it = 0; it < nk; it++) {
        float* buf = sm + (it & 1) * 8192;

        // ---- split + conflict-free wide stores ----
#pragma unroll
        for (int i = 0; i < 2; i++) {
            float b0 = cvt_tf32(av[i][0]), b1 = cvt_tf32(av[i][1]);
            float b2 = cvt_tf32(av[i][2]), b3 = cvt_tf32(av[i][3]);
            *(float4*)(buf + sAoff[i]) = make_float4(b0, b1, b2, b3);
            *(float4*)(buf + 2048 + sAoff[i]) =
                make_float4(cvt_tf32(av[i][0] - b0), cvt_tf32(av[i][1] - b1),
                            cvt_tf32(av[i][2] - b2), cvt_tf32(av[i][3] - b3));
        }
#pragma unroll
        for (int i = 0; i < 4; i++) {
            float b0 = cvt_tf32(bv[i][0]), b1 = cvt_tf32(bv[i][1]);
            *(float2*)(buf + 4096 + sBoff[i]) = make_float2(b0, b1);
            *(float2*)(buf + 6144 + sBoff[i]) =
                make_float2(cvt_tf32(bv[i][0] - b0), cvt_tf32(bv[i][1] - b1));
        }

        // ---- prefetch tile it+1 ----
        if (it + 1 < fullT) {
            // steady state: no guards
#pragma unroll
            for (int i = 0; i < 2; i++) {
                aP[i] += 16;
                av[i][0] = aP[i][0];
                av[i][1] = aP[i][8 * lda];
                av[i][2] = aP[i][4];
                av[i][3] = aP[i][8 * lda + 4];
            }
#pragma unroll
            for (int i = 0; i < 4; i++) {
                bP[i] += bAdv;
                bv[i][0] = bP[i][0] * nmask[i];
                bv[i][1] = bP[i][bStride] * nmask[i];
            }
        } else if (it + 1 < nk) {
            // tail tile: column-guarded (predicated loads keep addresses in-bounds)
            int kn = (it + 1) << 4;
#pragma unroll
            for (int i = 0; i < 2; i++) {
                aP[i] += 16;
                int c0 = kn + kofA[i], c1 = c0 + 4;
                float v0 = 0.f, v1 = 0.f, v2 = 0.f, v3 = 0.f;
                if (c0 < K) { v0 = aP[i][0]; v1 = aP[i][8 * lda]; }
                if (c1 < K) { v2 = aP[i][4]; v3 = aP[i][8 * lda + 4]; }
                av[i][0] = v0; av[i][1] = v1; av[i][2] = v2; av[i][3] = v3;
            }
#pragma unroll
            for (int i = 0; i < 4; i++) {
                bP[i] += bAdv;
                int c0 = kn + kofB[i], c1 = c0 + 4;
                float v0 = 0.f, v1 = 0.f;
                if (c0 < K) v0 = bP[i][0];
                if (c1 < K) v1 = bP[i][bStride];
                bv[i][0] = v0 * nmask[i];
                bv[i][1] = v1 * nmask[i];
            }
        }

        __syncthreads();

        // ---- MMA: hoisted fragment base pointers, base+immediate LDS ----
        const float4* aB4 = (const float4*)(buf + warp_m * 1024 + lane * 4);
        const float4* aS4 = (const float4*)(buf + 2048 + warp_m * 1024 + lane * 4);
        const float2* bB2 = (const float2*)(buf + 4096 + warp_n * 512 + lane * 2);
        const float2* bS2 = (const float2*)(buf + 6144 + warp_n * 512 + lane * 2);
#pragma unroll
        for (int kb = 0; kb < 2; kb++) {
            uint32_t afB[4][4], afS[4][4];
#pragma unroll
            for (int mi = 0; mi < 4; mi++) {
                float4 vb = aB4[mi * 64 + kb * 32];
                float4 vs = aS4[mi * 64 + kb * 32];
                afB[mi][0] = __float_as_uint(vb.x); afB[mi][1] = __float_as_uint(vb.y);
                afB[mi][2] = __float_as_uint(vb.z); afB[mi][3] = __float_as_uint(vb.w);
                afS[mi][0] = __float_as_uint(vs.x); afS[mi][1] = __float_as_uint(vs.y);
                afS[mi][2] = __float_as_uint(vs.z); afS[mi][3] = __float_as_uint(vs.w);
            }
            uint32_t bfB[4][2], bfS[4][2];
#pragma unroll
            for (int nj = 0; nj < 4; nj++) {
                float2 vb = bB2[nj * 64 + kb * 32];
                float2 vs = bS2[nj * 64 + kb * 32];
                bfB[nj][0] = __float_as_uint(vb.x); bfB[nj][1] = __float_as_uint(vb.y);
                bfS[nj][0] = __float_as_uint(vs.x); bfS[nj][1] = __float_as_uint(vs.y);
            }
#pragma unroll
            for (int mi = 0; mi < 4; mi++)
#pragma unroll
                for (int nj = 0; nj < 4; nj++) {
                    mma_tf32(acc[mi][nj], afS[mi], bfB[nj]);
                    mma_tf32(acc[mi][nj], afB[mi], bfS[nj]);
                    mma_tf32(acc[mi][nj], afB[mi], bfB[nj]);
                }
        }
        // no second sync: ping-pong buffer + next iteration's sync protect reuse
    }

    // ---- epilogue ----
    bool applyV = (vscale != nullptr) && (m0 >= vstart);
    const float* vs = vscale + (long)z * vzstride;
#pragma unroll
    for (int mi = 0; mi < 4; mi++) {
        int r0 = m0 + warp_m * 64 + mi * 16 + g;
        int r1 = r0 + 8;
        int o0 = permuteOut ? ((r0 & 511) * 16 + (r0 >> 9)) : r0;
        int o1 = permuteOut ? ((r1 & 511) * 16 + (r1 >> 9)) : r1;
        float* c0p = C + (long)o0 * ldc;
        float* c1p = C + (long)o1 * ldc;
#pragma unroll
        for (int nj = 0; nj < 4; nj++) {
            int col = n0 + warp_n * 32 + nj * 8 + 2 * tg;
            if (col >= N) continue;   // N even -> pair-guard safe
            float v0 = acc[mi][nj][0], v1 = acc[mi][nj][1];
            float v2 = acc[mi][nj][2], v3 = acc[mi][nj][3];
            if (bias) {
                float b0 = bias[col], b1 = bias[col + 1];
                v0 += b0; v1 += b1; v2 += b0; v3 += b1;
            }
            if (doRelu) {
                v0 = fmaxf(v0, 0.f); v1 = fmaxf(v1, 0.f);
                v2 = fmaxf(v2, 0.f); v3 = fmaxf(v3, 0.f);
            }
            if (applyV) {
                float s0 = vs[col], s1 = vs[col + 1];
                v0 *= s0; v1 *= s1; v2 *= s0; v3 *= s1;
            }
            *(float2*)(c0p + col) = make_float2(v0, v1);
            *(float2*)(c1p + col) = make_float2(v2, v3);
        }
    }
}

// ---------------- masked softmax over rows of g_scores ----------------
__global__ void softmax_rows(const unsigned char* __restrict__ mask) {
    int r = blockIdx.x;          // b*512 + l
    int b = r >> 9;
    float* row = g_scores + (long)r * LL2;
    __shared__ float red[256];
    int t = threadIdx.x;

    float v0 = row[t];
    float v1 = row[t + 256];
    if (mask[b * LL2 + t]) v0 = -3.402823466e38f;
    if (mask[b * LL2 + t + 256]) v1 = -3.402823466e38f;

    float mx = fmaxf(v0, v1);
    red[t] = mx;
    __syncthreads();
    for (int s = 128; s > 0; s >>= 1) {
        if (t < s) red[t] = fmaxf(red[t], red[t + s]);
        __syncthreads();
    }
    mx = red[0];
    __syncthreads();

    v0 = __expf(v0 - mx);
    v1 = __expf(v1 - mx);
    red[t] = v0 + v1;
    __syncthreads();
    for (int s = 128; s > 0; s >>= 1) {
        if (t < s) red[t] += red[t + s];
        __syncthreads();
    }
    float inv = 1.f / red[0];
    row[t] = v0 * inv;
    row[t + 256] = v1 * inv;
}

// ---------------- BiLSTM recurrence ----------------
// 512 threads; thread j computes z[j]. Whh row j: k 0..95 in registers (48 f32x2
// pairs), k 96..127 in shared ([8][512] float4, conflict-free LDS.128).
// Dot products via packed fma.rn.f32x2 (FFMA2: 2 MACs/instr).
__global__ void __launch_bounds__(512, 1)
lstm_kernel(const float* __restrict__ WhhF, const float* __restrict__ WhhB,
            float* __restrict__ out) {
    extern __shared__ float sm[];
    float4* sW4 = (float4*)sm;              // [8][512] float4 = 64KB
    float* h_sh = sm + 8 * 512 * 4;         // [128]
    float* z_sh = h_sh + 128;               // [512]

    int b = blockIdx.x;
    int dir = blockIdx.y;
    const float* Whh = dir ? WhhB : WhhF;
    int j = threadIdx.x;

    unsigned long long wp[48];
#pragma unroll
    for (int k2 = 0; k2 < 48; k2++)
        wp[k2] = *(const unsigned long long*)&Whh[j * HID + 2 * k2];
#pragma unroll
    for (int k4 = 0; k4 < 8; k4++) {
        const float* ws = Whh + j * HID + 96 + 4 * k4;
        sW4[k4 * 512 + j] = make_float4(ws[0], ws[1], ws[2], ws[3]);
    }
    if (j < HID) h_sh[j] = 0.f;
    float c = 0.f;
    __syncthreads();

    int gofs = dir * 512 + j;
    int l0 = dir ? (LL1 - 1) : 0;
    float gcur = g_gin[((long)l0 * BB + b) * 1024 + gofs];

    for (int s = 0; s < LL1; s++) {
        int l = dir ? (LL1 - 1 - s) : s;
        float gnext = 0.f;
        if (s + 1 < LL1) {
            int ln = dir ? (LL1 - 2 - s) : (s + 1);
            gnext = g_gin[((long)ln * BB + b) * 1024 + gofs];
        }

        unsigned long long acc2;
        {
            uint32_t lo = __float_as_uint(gcur);
            asm("mov.b64 %0, {%1, %2};" : "=l"(acc2) : "r"(lo), "r"(0u));
        }
        const unsigned long long* hp = (const unsigned long long*)h_sh;
#pragma unroll
        for (int k2 = 0; k2 < 48; k2++)
            acc2 = fma2_(hp[k2], wp[k2], acc2);
#pragma unroll
        for (int k4 = 0; k4 < 8; k4++) {
            ulonglong2 w2 = *(const ulonglong2*)&sW4[k4 * 512 + j];
            ulonglong2 h2 = *(const ulonglong2*)&h_sh[96 + 4 * k4];
            acc2 = fma2_(h2.x, w2.x, acc2);
            acc2 = fma2_(h2.y, w2.y, acc2);
        }
        uint32_t ulo, uhi;
        asm("mov.b64 {%0, %1}, %2;" : "=r"(ulo), "=r"(uhi) : "l"(acc2));
        z_sh[j] = __uint_as_float(ulo) + __uint_as_float(uhi);
        __syncthreads();
        if (j < HID) {
            float zi = z_sh[j], zf = z_sh[j + 128], zg = z_sh[j + 256], zo = z_sh[j + 384];
            float ii = 1.f / (1.f + __expf(-zi));
            float ff = 1.f / (1.f + __expf(-zf));
            float ag = fabsf(zg);
            float gg = copysignf(1.f - 2.f / (__expf(2.f * ag) + 1.f), zg);
            float oo = 1.f / (1.f + __expf(-zo));
            c = ff * c + ii * gg;
            float ac = fabsf(c);
            float tc = copysignf(1.f - 2.f / (__expf(2.f * ac) + 1.f), c);
            float h = oo * tc;
            h_sh[j] = h;
            out[((long)b * LL1 + l) * 256 + dir * HID + j] = h;
        }
        gcur = gnext;
        __syncthreads();
    }
}

// ---------------- launcher ----------------
extern "C" void kernel_launch(void* const* d_in, const int* in_sizes, int n_in,
                              void* d_out, int out_size) {
    const float* x1_word = (const float*)d_in[0];
    const float* x1_a0   = (const float*)d_in[1];
    const float* x1_a1   = (const float*)d_in[2];
    const float* x2_word = (const float*)d_in[3];
    const float* x2_a0   = (const float*)d_in[4];
    const float* x2_a1   = (const float*)d_in[5];
    const float* x2_a2   = (const float*)d_in[6];
    const unsigned char* x2_mask = (const unsigned char*)d_in[8];
    const float* W_attn  = (const float*)d_in[9];
    const float* v_attn  = (const float*)d_in[10];
    const float* Wih_f   = (const float*)d_in[11];
    const float* Whh_f   = (const float*)d_in[12];
    const float* b_f     = (const float*)d_in[13];
    const float* Wih_b   = (const float*)d_in[14];
    const float* Whh_b   = (const float*)d_in[15];
    const float* b_b     = (const float*)d_in[16];
    float* out = (float*)d_out;

    float *xatt, *rbuf, *scores, *x1cat, *wih, *bih, *ginbuf;
    cudaGetSymbolAddress((void**)&xatt, g_xatt);
    cudaGetSymbolAddress((void**)&rbuf, g_r);
    cudaGetSymbolAddress((void**)&scores, g_scores);
    cudaGetSymbolAddress((void**)&x1cat, g_x1cat);
    cudaGetSymbolAddress((void**)&wih, g_Wih);
    cudaGetSymbolAddress((void**)&bih, g_bih);
    cudaGetSymbolAddress((void**)&ginbuf, g_gin);

    const int GEMM_SMEM = 2 * 8192 * 4;  // 64 KB (double-buffered frag tiles)
    cudaFuncSetAttribute(gemm_tc, cudaFuncAttributeMaxDynamicSharedMemorySize, GEMM_SMEM);

    // concat inputs
    {
        long n1 = (long)2 * BB * 512 * ATT_IN;
        build_xatt<<<(int)((n1 + 255) / 256), 256>>>(x1_word, x1_a0, x1_a1,
                                                     x2_word, x2_a0, x2_a1);
        int n3 = BB * LL1 * 512;
        build_x1cat_head<<<(n3 + 255) / 256, 256>>>(x1_a0, x1_a1);
        int n4 = 1024 * RNN_IN;
        build_wih<<<(n4 + 255) / 256, 256>>>(Wih_f, Wih_b, b_f, b_b);
    }

    // r = relu([x1att; x2att] @ Wi^T), batched over 3 heads; v applied to x2 rows
    gemm_tc<<<dim3(2, 128, 3), 256, GEMM_SMEM>>>(xatt, ATT_IN, 0,
                                      W_attn, ATT_IN, (long)ATTD * ATT_IN, 1,
                                      rbuf, 256, (long)16384 * 256,
                                      16384, ATTD, ATT_IN,
                                      nullptr, v_attn, ATTD, 8192, 1, 0);

    const float* x2_list[3] = {x2_a0, x2_a1, x2_a2};
    for (int i = 0; i < 3; i++) {
        const float* r1 = rbuf + (long)i * 16384 * 256;
        const float* r2 = r1 + (long)8192 * 256;

        // scores[b] = r1[b] @ r2[b]^T  batched 16 x [512 x 512], K=250
        gemm_tc<<<dim3(4, 4, 16), 256, GEMM_SMEM>>>(r1, 256, (long)512 * 256,
                                         r2, 256, (long)512 * 256, 1,
                                         scores, 512, (long)512 * 512,
                                         LL1, LL2, ATTD,
                                         nullptr, nullptr, 0, 0, 0, 0);
        softmax_rows<<<BB * LL1, 256>>>(x2_mask);
        // piece_i[b] = alpha[b] @ x2_list[i][b] -> x1cat cols [512+256i, +256)
        gemm_tc<<<dim3(2, 4, 16), 256, GEMM_SMEM>>>(scores, 512, (long)512 * 512,
                                         x2_list[i], 256, (long)512 * 256, 0,
                                         x1cat + 512 + 256 * i, RNN_IN, (long)512 * RNN_IN,
                                         LL1, AH, LL2,
                                         nullptr, nullptr, 0, 0, 0, 0);
    }

    // g_in (both dirs) = x1cat @ [Wih_f; Wih_b]^T + b, rows permuted to [l*16+b]
    gemm_tc<<<dim3(8, 64, 1), 256, GEMM_SMEM>>>(x1cat, RNN_IN, 0, wih, RNN_IN, 0, 1,
                                     ginbuf, 1024, 0, BB * LL1, 1024, RNN_IN,
                                     bih, nullptr, 0, 0, 0, 1);

    // BiLSTM
    size_t smem = (size_t)(8 * 512 * 4 + 128 + 512) * sizeof(float);
    cudaFuncSetAttribute(lstm_kernel, cudaFuncAttributeMaxDynamicSharedMemorySize, (int)smem);
    lstm_kernel<<<dim3(16, 2), 512, smem>>>(Whh_f, Whh_b, out);
}

// round 8
// speedup vs baseline: 1.8701x; 1.3888x over previous
#include <cuda_runtime.h>
#include <math.h>
#include <stdint.h>

#define BB 16
#define LL1 512
#define LL2 512
#define EMB 300
#define AH 256
#define ATTD 250
#define HID 128
#define ATT_IN 812
#define RNN_IN 1280
#define GATES 512  // 4*HID

// ---------------- scratch (device globals; no allocation allowed) ----------------
__device__ float g_xatt[2 * BB * 512 * ATT_IN];   // x1att rows 0..8191, x2att rows 8192..16383
__device__ float g_r[3 * 16384 * 256];            // per head: [16384][256] (ATTD padded)
__device__ float g_scores[BB * LL1 * LL2];
__device__ float g_x1cat[BB * LL1 * RNN_IN];
__device__ float g_gin[LL1 * BB * 1024];          // [l*16+b][dir*512 + gate]
__device__ float g_Wih[1024 * RNN_IN];            // rows 0..511 fwd, 512..1023 bwd
__device__ float g_bih[1024];

// ---------------- concat builders ----------------
__global__ void build_xatt(const float* __restrict__ w1, const float* __restrict__ a10,
                           const float* __restrict__ a11, const float* __restrict__ w2,
                           const float* __restrict__ a20, const float* __restrict__ a21) {
    long idx = (long)blockIdx.x * blockDim.x + threadIdx.x;
    if (idx >= (long)2 * BB * 512 * ATT_IN) return;
    int c = (int)(idx % ATT_IN);
    long row = idx / ATT_IN;
    const float* w = w1; const float* a0 = a10; const float* a1 = a11;
    long r = row;
    if (row >= (long)BB * 512) { w = w2; a0 = a20; a1 = a21; r = row - BB * 512; }
    float v;
    if (c < EMB) v = w[r * EMB + c];
    else if (c < EMB + AH) v = a0[r * AH + (c - EMB)];
    else v = a1[r * AH + (c - EMB - AH)];
    g_xatt[idx] = v;
}

__global__ void build_x1cat_head(const float* __restrict__ a0, const float* __restrict__ a1) {
    int idx = blockIdx.x * blockDim.x + threadIdx.x;
    if (idx >= BB * LL1 * 512) return;
    int c = idx % 512;
    int r = idx / 512;
    float v = (c < 256) ? a0[r * 256 + c] : a1[r * 256 + (c - 256)];
    g_x1cat[(long)r * RNN_IN + c] = v;
}

__global__ void build_wih(const float* __restrict__ Wf, const float* __restrict__ Wb,
                          const float* __restrict__ bf, const float* __restrict__ bb) {
    int idx = blockIdx.x * blockDim.x + threadIdx.x;
    if (idx < 1024) g_bih[idx] = (idx < 512) ? bf[idx] : bb[idx - 512];
    if (idx >= 1024 * RNN_IN) return;
    int row = idx / RNN_IN;
    int col = idx % RNN_IN;
    g_Wih[idx] = (row < 512) ? Wf[row * RNN_IN + col] : Wb[(row - 512) * RNN_IN + col];
}

// ---------------- bf16 / f32x2 helpers ----------------
// pack two floats to bf16x2: lo -> low 16 bits, hi -> high 16 bits
__device__ __forceinline__ uint32_t pack_bf16(float lo, float hi) {
    uint32_t r;
    asm("cvt.rn.bf16x2.f32 %0, %1, %2;" : "=r"(r) : "f"(hi), "f"(lo));
    return r;
}

// split pair into big (bf16x2) and small (bf16x2 of residual)
__device__ __forceinline__ void split_bf16(float lo, float hi, uint32_t& big, uint32_t& small) {
    big = pack_bf16(lo, hi);
    float blo = __uint_as_float(big << 16);
    float bhi = __uint_as_float(big & 0xffff0000u);
    small = pack_bf16(lo - blo, hi - bhi);
}

__device__ __forceinline__ void mma_bf16(float* d, const uint32_t* a, const uint32_t* b) {
    asm volatile(
        "mma.sync.aligned.m16n8k16.row.col.f32.bf16.bf16.f32 "
        "{%0,%1,%2,%3}, {%4,%5,%6,%7}, {%8,%9}, {%0,%1,%2,%3};"
        : "+f"(d[0]), "+f"(d[1]), "+f"(d[2]), "+f"(d[3])
        : "r"(a[0]), "r"(a[1]), "r"(a[2]), "r"(a[3]), "r"(b[0]), "r"(b[1]));
}

__device__ __forceinline__ unsigned long long fma2_(unsigned long long a,
                                                   unsigned long long b,
                                                   unsigned long long c) {
    unsigned long long d;
    asm("fma.rn.f32x2 %0, %1, %2, %3;" : "=l"(d) : "l"(a), "l"(b), "l"(c));
    return d;
}

// ---------- 3xBF16 tensor-core GEMM: 128x128 block, 8 warps (2m x 4n) ----------
// C = A * B' (+bias, relu, vscale, permuted rows); B' = B^T if transB.
// K-step 16 = one m16n8k16 MMA. Split big/small bf16; acc += As*Bb + Ab*Bs + Ab*Bb.
// Fragment staging: thread t owns A-quad t (STS.128) and B-pairs t, t+256 (STS.64);
// all consecutive-address -> conflict-free. Double-buffered smem (2 x 16KB),
// one __syncthreads per k-tile.
__global__ void __launch_bounds__(256, 2)
gemm_tc(const float* __restrict__ A, int lda, long sA,
        const float* __restrict__ Bm, int ldb, long sB, int transB,
        float* __restrict__ C, int ldc, long sC,
        int M, int N, int K,
        const float* __restrict__ bias,
        const float* __restrict__ vscale, int vzstride, int vstart,
        int doRelu, int permuteOut) {
    extern __shared__ uint32_t smu[];

    int z = blockIdx.z;
    A += z * sA;
    Bm += z * sB;
    C += z * sC;

    int m0 = blockIdx.y * 128;
    int n0 = blockIdx.x * 128;
    int tid = threadIdx.x;
    int wid = tid >> 5;
    int lane = tid & 31;
    int g = lane >> 2;
    int tg = lane & 3;
    int warp_m = wid & 1;
    int warp_n = wid >> 1;

    float acc[4][4][4];
#pragma unroll
    for (int i = 0; i < 4; i++)
#pragma unroll
        for (int j = 0; j < 4; j++)
#pragma unroll
            for (int q = 0; q < 4; q++) acc[i][j][q] = 0.f;

    // ---- A staging ownership: quad q = tid; mt=q>>5, l=q&31, r=l>>2, c=l&3 ----
    int a_mt = tid >> 5;
    int a_r = (tid & 31) >> 2;
    int a_c = (tid & 3) * 2;                 // k-col base (even)
    int rowa = m0 + a_mt * 16 + a_r;         // always < M (M % 128 == 0)
    const float* aP = A + (long)rowa * lda + a_c;
    long aRow8 = (long)8 * lda;

    // ---- B staging ownership: pairs p = tid, tid+256 ----
    int bN[2], bC[2];
    float nmask[2];
    const float* bP[2];
    long ldbL = ldb;
#pragma unroll
    for (int i = 0; i < 2; i++) {
        int p = tid + 256 * i;
        int l = p & 31;
        bN[i] = n0 + (p >> 5) * 8 + (l >> 2);
        bC[i] = (l & 3) * 2;
        nmask[i] = (bN[i] < N) ? 1.f : 0.f;
        int nc = (bN[i] < N) ? bN[i] : (N - 1);
        bP[i] = transB ? (Bm + (long)nc * ldbL + bC[i])
                       : (Bm + (long)bC[i] * ldbL + nc);
    }
    long bAdv = transB ? 16 : 16 * ldbL;

    float av[8];     // A: (r,c),(r,c+1),(r+8,c),(r+8,c+1),(r,c+8),(r,c+9),(r+8,c+8),(r+8,c+9)
    float bv[2][4];  // per pair: (k=c,n),(k=c+1,n),(k=c+8,n),(k=c+9,n)

    int fullT = K >> 4;
    int nk = (K + 15) >> 4;

    // ---- prologue: guarded load of tile 0 ----
    {
        int c0 = a_c, c1 = a_c + 1, c2 = a_c + 8, c3 = a_c + 9;
        av[0] = (c0 < K) ? aP[0] : 0.f;
        av[1] = (c1 < K) ? aP[1] : 0.f;
        av[2] = (c0 < K) ? aP[aRow8] : 0.f;
        av[3] = (c1 < K) ? aP[aRow8 + 1] : 0.f;
        av[4] = (c2 < K) ? aP[8] : 0.f;
        av[5] = (c3 < K) ? aP[9] : 0.f;
        av[6] = (c2 < K) ? aP[aRow8 + 8] : 0.f;
        av[7] = (c3 < K) ? aP[aRow8 + 9] : 0.f;
#pragma unroll
        for (int i = 0; i < 2; i++) {
            int c0b = bC[i], c1b = bC[i] + 1, c2b = bC[i] + 8, c3b = bC[i] + 9;
            float v0, v1, v2, v3;
            if (transB) {
                v0 = (c0b < K) ? bP[i][0] : 0.f;
                v1 = (c1b < K) ? bP[i][1] : 0.f;
                v2 = (c2b < K) ? bP[i][8] : 0.f;
                v3 = (c3b < K) ? bP[i][9] : 0.f;
            } else {
                v0 = (c0b < K) ? bP[i][0] : 0.f;
                v1 = (c1b < K) ? bP[i][ldbL] : 0.f;
                v2 = (c2b < K) ? bP[i][8 * ldbL] : 0.f;
                v3 = (c3b < K) ? bP[i][9 * ldbL] : 0.f;
            }
            bv[i][0] = v0 * nmask[i]; bv[i][1] = v1 * nmask[i];
            bv[i][2] = v2 * nmask[i]; bv[i][3] = v3 * nmask[i];
        }
    }

    for (int it = 0; it < nk; it++) {
        uint32_t* buf = smu + (it & 1) * 4096;
        uint32_t* AfB = buf;            // 1024 u32
        uint32_t* AfS = buf + 1024;
        uint32_t* BfB = buf + 2048;
        uint32_t* BfS = buf + 3072;

        // ---- split + conflict-free wide stores ----
        {
            uint32_t b0, s0, b1, s1, b2, s2, b3, s3;
            split_bf16(av[0], av[1], b0, s0);
            split_bf16(av[2], av[3], b1, s1);
            split_bf16(av[4], av[5], b2, s2);
            split_bf16(av[6], av[7], b3, s3);
            *(uint4*)(AfB + tid * 4) = make_uint4(b0, b1, b2, b3);
            *(uint4*)(AfS + tid * 4) = make_uint4(s0, s1, s2, s3);
        }
#pragma unroll
        for (int i = 0; i < 2; i++) {
            int p = tid + 256 * i;
            uint32_t b0, s0, b1, s1;
            split_bf16(bv[i][0], bv[i][1], b0, s0);
            split_bf16(bv[i][2], bv[i][3], b1, s1);
            *(uint2*)(BfB + p * 2) = make_uint2(b0, b1);
            *(uint2*)(BfS + p * 2) = make_uint2(s0, s1);
        }

        // ---- prefetch next k-tile into regs ----
        if (it + 1 < fullT) {
            aP += 16;
            float2 x0 = *(const float2*)aP;
            float2 x1 = *(const float2*)(aP + aRow8);
            float2 x2 = *(const float2*)(aP + 8);
            float2 x3 = *(const float2*)(aP + aRow8 + 8);
            av[0] = x0.x; av[1] = x0.y; av[2] = x1.x; av[3] = x1.y;
            av[4] = x2.x; av[5] = x2.y; av[6] = x3.x; av[7] = x3.y;
            if (transB) {
#pragma unroll
                for (int i = 0; i < 2; i++) {
                    bP[i] += bAdv;
                    float2 y0 = *(const float2*)bP[i];
                    float2 y1 = *(const float2*)(bP[i] + 8);
                    bv[i][0] = y0.x * nmask[i]; bv[i][1] = y0.y * nmask[i];
                    bv[i][2] = y1.x * nmask[i]; bv[i][3] = y1.y * nmask[i];
                }
            } else {
#pragma unroll
                for (int i = 0; i < 2; i++) {
                    bP[i] += bAdv;
                    bv[i][0] = bP[i][0] * nmask[i];
                    bv[i][1] = bP[i][ldbL] * nmask[i];
                    bv[i][2] = bP[i][8 * ldbL] * nmask[i];
                    bv[i][3] = bP[i][9 * ldbL] * nmask[i];
                }
            }
        } else if (it + 1 < nk) {
            int kb = (it + 1) << 4;
            aP += 16;
            int c0 = kb + a_c, c1 = c0 + 1, c2 = c0 + 8, c3 = c0 + 9;
            av[0] = (c0 < K) ? aP[0] : 0.f;
            av[1] = (c1 < K) ? aP[1] : 0.f;
            av[2] = (c0 < K) ? aP[aRow8] : 0.f;
            av[3] = (c1 < K) ? aP[aRow8 + 1] : 0.f;
            av[4] = (c2 < K) ? aP[8] : 0.f;
            av[5] = (c3 < K) ? aP[9] : 0.f;
            av[6] = (c2 < K) ? aP[aRow8 + 8] : 0.f;
            av[7] = (c3 < K) ? aP[aRow8 + 9] : 0.f;
#pragma unroll
            for (int i = 0; i < 2; i++) {
                bP[i] += bAdv;
                int c0b = kb + bC[i], c1b = c0b + 1, c2b = c0b + 8, c3b = c0b + 9;
                float v0, v1, v2, v3;
                if (transB) {
                    v0 = (c0b < K) ? bP[i][0] : 0.f;
                    v1 = (c1b < K) ? bP[i][1] : 0.f;
                    v2 = (c2b < K) ? bP[i][8] : 0.f;
                    v3 = (c3b < K) ? bP[i][9] : 0.f;
                } else {
                    v0 = (c0b < K) ? bP[i][0] : 0.f;
                    v1 = (c1b < K) ? bP[i][ldbL] : 0.f;
                    v2 = (c2b < K) ? bP[i][8 * ldbL] : 0.f;
                    v3 = (c3b < K) ? bP[i][9 * ldbL] : 0.f;
                }
                bv[i][0] = v0 * nmask[i]; bv[i][1] = v1 * nmask[i];
                bv[i][2] = v2 * nmask[i]; bv[i][3] = v3 * nmask[i];
            }
        }

        __syncthreads();

        // ---- MMA: 16 fragments x 3 (k16 per MMA) ----
        const uint4* aB4 = (const uint4*)(AfB + warp_m * 512 + lane * 4);
        const uint4* aS4 = (const uint4*)(AfS + warp_m * 512 + lane * 4);
        const uint2* bB2 = (const uint2*)(BfB + warp_n * 256 + lane * 2);
        const uint2* bS2 = (const uint2*)(BfS + warp_n * 256 + lane * 2);
        uint32_t afB[4][4], afS[4][4], bfB[4][2], bfS[4][2];
#pragma unroll
        for (int mi = 0; mi < 4; mi++) {
            uint4 vb = aB4[mi * 32];
            uint4 vs = aS4[mi * 32];
            afB[mi][0] = vb.x; afB[mi][1] = vb.y; afB[mi][2] = vb.z; afB[mi][3] = vb.w;
            afS[mi][0] = vs.x; afS[mi][1] = vs.y; afS[mi][2] = vs.z; afS[mi][3] = vs.w;
        }
#pragma unroll
        for (int nj = 0; nj < 4; nj++) {
            uint2 vb = bB2[nj * 32];
            uint2 vs = bS2[nj * 32];
            bfB[nj][0] = vb.x; bfB[nj][1] = vb.y;
            bfS[nj][0] = vs.x; bfS[nj][1] = vs.y;
        }
#pragma unroll
        for (int mi = 0; mi < 4; mi++)
#pragma unroll
            for (int nj = 0; nj < 4; nj++) {
                mma_bf16(acc[mi][nj], afS[mi], bfB[nj]);
                mma_bf16(acc[mi][nj], afB[mi], bfS[nj]);
                mma_bf16(acc[mi][nj], afB[mi], bfB[nj]);
            }
        // no second sync: ping-pong buffer + next iteration's sync protect reuse
    }

    // ---- epilogue ----
    bool applyV = (vscale != nullptr) && (m0 >= vstart);
    const float* vs = vscale + (long)z * vzstride;
#pragma unroll
    for (int mi = 0; mi < 4; mi++) {
        int r0 = m0 + warp_m * 64 + mi * 16 + g;
        int r1 = r0 + 8;
        int o0 = permuteOut ? ((r0 & 511) * 16 + (r0 >> 9)) : r0;
        int o1 = permuteOut ? ((r1 & 511) * 16 + (r1 >> 9)) : r1;
        float* c0p = C + (long)o0 * ldc;
        float* c1p = C + (long)o1 * ldc;
#pragma unroll
        for (int nj = 0; nj < 4; nj++) {
            int col = n0 + warp_n * 32 + nj * 8 + 2 * tg;
            if (col >= N) continue;   // N even -> pair-guard safe
            float v0 = acc[mi][nj][0], v1 = acc[mi][nj][1];
            float v2 = acc[mi][nj][2], v3 = acc[mi][nj][3];
            if (bias) {
                float b0 = bias[col], b1 = bias[col + 1];
                v0 += b0; v1 += b1; v2 += b0; v3 += b1;
            }
            if (doRelu) {
                v0 = fmaxf(v0, 0.f); v1 = fmaxf(v1, 0.f);
                v2 = fmaxf(v2, 0.f); v3 = fmaxf(v3, 0.f);
            }
            if (applyV) {
                float s0 = vs[col], s1 = vs[col + 1];
                v0 *= s0; v1 *= s1; v2 *= s0; v3 *= s1;
            }
            *(float2*)(c0p + col) = make_float2(v0, v1);
            *(float2*)(c1p + col) = make_float2(v2, v3);
        }
    }
}

// ---------------- masked softmax over rows of g_scores ----------------
__global__ void softmax_rows(const unsigned char* __restrict__ mask) {
    int r = blockIdx.x;          // b*512 + l
    int b = r >> 9;
    float* row = g_scores + (long)r * LL2;
    __shared__ float red[256];
    int t = threadIdx.x;

    float v0 = row[t];
    float v1 = row[t + 256];
    if (mask[b * LL2 + t]) v0 = -3.402823466e38f;
    if (mask[b * LL2 + t + 256]) v1 = -3.402823466e38f;

    float mx = fmaxf(v0, v1);
    red[t] = mx;
    __syncthreads();
    for (int s = 128; s > 0; s >>= 1) {
        if (t < s) red[t] = fmaxf(red[t], red[t + s]);
        __syncthreads();
    }
    mx = red[0];
    __syncthreads();

    v0 = __expf(v0 - mx);
    v1 = __expf(v1 - mx);
    red[t] = v0 + v1;
    __syncthreads();
    for (int s = 128; s > 0; s >>= 1) {
        if (t < s) red[t] += red[t + s];
        __syncthreads();
    }
    float inv = 1.f / red[0];
    row[t] = v0 * inv;
    row[t + 256] = v1 * inv;
}

// ---------------- BiLSTM recurrence ----------------
__global__ void __launch_bounds__(512, 1)
lstm_kernel(const float* __restrict__ WhhF, const float* __restrict__ WhhB,
            float* __restrict__ out) {
    extern __shared__ float sm[];
    float4* sW4 = (float4*)sm;              // [8][512] float4 = 64KB
    float* h_sh = sm + 8 * 512 * 4;         // [128]
    float* z_sh = h_sh + 128;               // [512]

    int b = blockIdx.x;
    int dir = blockIdx.y;
    const float* Whh = dir ? WhhB : WhhF;
    int j = threadIdx.x;

    unsigned long long wp[48];
#pragma unroll
    for (int k2 = 0; k2 < 48; k2++)
        wp[k2] = *(const unsigned long long*)&Whh[j * HID + 2 * k2];
#pragma unroll
    for (int k4 = 0; k4 < 8; k4++) {
        const float* ws = Whh + j * HID + 96 + 4 * k4;
        sW4[k4 * 512 + j] = make_float4(ws[0], ws[1], ws[2], ws[3]);
    }
    if (j < HID) h_sh[j] = 0.f;
    float c = 0.f;
    __syncthreads();

    int gofs = dir * 512 + j;
    int l0 = dir ? (LL1 - 1) : 0;
    float gcur = g_gin[((long)l0 * BB + b) * 1024 + gofs];

    for (int s = 0; s < LL1; s++) {
        int l = dir ? (LL1 - 1 - s) : s;
        float gnext = 0.f;
        if (s + 1 < LL1) {
            int ln = dir ? (LL1 - 2 - s) : (s + 1);
            gnext = g_gin[((long)ln * BB + b) * 1024 + gofs];
        }

        unsigned long long acc2;
        {
            uint32_t lo = __float_as_uint(gcur);
            asm("mov.b64 %0, {%1, %2};" : "=l"(acc2) : "r"(lo), "r"(0u));
        }
        const unsigned long long* hp = (const unsigned long long*)h_sh;
#pragma unroll
        for (int k2 = 0; k2 < 48; k2++)
            acc2 = fma2_(hp[k2], wp[k2], acc2);
#pragma unroll
        for (int k4 = 0; k4 < 8; k4++) {
            ulonglong2 w2 = *(const ulonglong2*)&sW4[k4 * 512 + j];
            ulonglong2 h2 = *(const ulonglong2*)&h_sh[96 + 4 * k4];
            acc2 = fma2_(h2.x, w2.x, acc2);
            acc2 = fma2_(h2.y, w2.y, acc2);
        }
        uint32_t ulo, uhi;
        asm("mov.b64 {%0, %1}, %2;" : "=r"(ulo), "=r"(uhi) : "l"(acc2));
        z_sh[j] = __uint_as_float(ulo) + __uint_as_float(uhi);
        __syncthreads();
        if (j < HID) {
            float zi = z_sh[j], zf = z_sh[j + 128], zg = z_sh[j + 256], zo = z_sh[j + 384];
            float ii = 1.f / (1.f + __expf(-zi));
            float ff = 1.f / (1.f + __expf(-zf));
            float ag = fabsf(zg);
            float gg = copysignf(1.f - 2.f / (__expf(2.f * ag) + 1.f), zg);
            float oo = 1.f / (1.f + __expf(-zo));
            c = ff * c + ii * gg;
            float ac = fabsf(c);
            float tc = copysignf(1.f - 2.f / (__expf(2.f * ac) + 1.f), c);
            float h = oo * tc;
            h_sh[j] = h;
            out[((long)b * LL1 + l) * 256 + dir * HID + j] = h;
        }
        gcur = gnext;
        __syncthreads();
    }
}

// ---------------- launcher ----------------
extern "C" void kernel_launch(void* const* d_in, const int* in_sizes, int n_in,
                              void* d_out, int out_size) {
    const float* x1_word = (const float*)d_in[0];
    const float* x1_a0   = (const float*)d_in[1];
    const float* x1_a1   = (const float*)d_in[2];
    const float* x2_word = (const float*)d_in[3];
    const float* x2_a0   = (const float*)d_in[4];
    const float* x2_a1   = (const float*)d_in[5];
    const float* x2_a2   = (const float*)d_in[6];
    const unsigned char* x2_mask = (const unsigned char*)d_in[8];
    const float* W_attn  = (const float*)d_in[9];
    const float* v_attn  = (const float*)d_in[10];
    const float* Wih_f   = (const float*)d_in[11];
    const float* Whh_f   = (const float*)d_in[12];
    const float* b_f     = (const float*)d_in[13];
    const float* Wih_b   = (const float*)d_in[14];
    const float* Whh_b   = (const float*)d_in[15];
    const float* b_b     = (const float*)d_in[16];
    float* out = (float*)d_out;

    float *xatt, *rbuf, *scores, *x1cat, *wih, *bih, *ginbuf;
    cudaGetSymbolAddress((void**)&xatt, g_xatt);
    cudaGetSymbolAddress((void**)&rbuf, g_r);
    cudaGetSymbolAddress((void**)&scores, g_scores);
    cudaGetSymbolAddress((void**)&x1cat, g_x1cat);
    cudaGetSymbolAddress((void**)&wih, g_Wih);
    cudaGetSymbolAddress((void**)&bih, g_bih);
    cudaGetSymbolAddress((void**)&ginbuf, g_gin);

    const int GEMM_SMEM = 2 * 4096 * 4;  // 32 KB (double-buffered bf16 frag tiles)
    cudaFuncSetAttribute(gemm_tc, cudaFuncAttributeMaxDynamicSharedMemorySize, GEMM_SMEM);

    // concat inputs
    {
        long n1 = (long)2 * BB * 512 * ATT_IN;
        build_xatt<<<(int)((n1 + 255) / 256), 256>>>(x1_word, x1_a0, x1_a1,
                                                     x2_word, x2_a0, x2_a1);
        int n3 = BB * LL1 * 512;
        build_x1cat_head<<<(n3 + 255) / 256, 256>>>(x1_a0, x1_a1);
        int n4 = 1024 * RNN_IN;
        build_wih<<<(n4 + 255) / 256, 256>>>(Wih_f, Wih_b, b_f, b_b);
    }

    // r = relu([x1att; x2att] @ Wi^T), batched over 3 heads; v applied to x2 rows
    gemm_tc<<<dim3(2, 128, 3), 256, GEMM_SMEM>>>(xatt, ATT_IN, 0,
                                      W_attn, ATT_IN, (long)ATTD * ATT_IN, 1,
                                      rbuf, 256, (long)16384 * 256,
                                      16384, ATTD, ATT_IN,
                                      nullptr, v_attn, ATTD, 8192, 1, 0);

    const float* x2_list[3] = {x2_a0, x2_a1, x2_a2};
    for (int i = 0; i < 3; i++) {
        const float* r1 = rbuf + (long)i * 16384 * 256;
        const float* r2 = r1 + (long)8192 * 256;

        // scores[b] = r1[b] @ r2[b]^T  batched 16 x [512 x 512], K=250
        gemm_tc<<<dim3(4, 4, 16), 256, GEMM_SMEM>>>(r1, 256, (long)512 * 256,
                                         r2, 256, (long)512 * 256, 1,
                                         scores, 512, (long)512 * 512,
                                         LL1, LL2, ATTD,
                                         nullptr, nullptr, 0, 0, 0, 0);
        softmax_rows<<<BB * LL1, 256>>>(x2_mask);
        // piece_i[b] = alpha[b] @ x2_list[i][b] -> x1cat cols [512+256i, +256)
        gemm_tc<<<dim3(2, 4, 16), 256, GEMM_SMEM>>>(scores, 512, (long)512 * 512,
                                         x2_list[i], 256, (long)512 * 256, 0,
                                         x1cat + 512 + 256 * i, RNN_IN, (long)512 * RNN_IN,
                                         LL1, AH, LL2,
                                         nullptr, nullptr, 0, 0, 0, 0);
    }

    // g_in (both dirs) = x1cat @ [Wih_f; Wih_b]^T + b, rows permuted to [l*16+b]
    gemm_tc<<<dim3(8, 64, 1), 256, GEMM_SMEM>>>(x1cat, RNN_IN, 0, wih, RNN_IN, 0, 1,
                                     ginbuf, 1024, 0, BB * LL1, 1024, RNN_IN,
                                     bih, nullptr, 0, 0, 0, 1);

    // BiLSTM
    size_t smem = (size_t)(8 * 512 * 4 + 128 + 512) * sizeof(float);
    cudaFuncSetAttribute(lstm_kernel, cudaFuncAttributeMaxDynamicSharedMemorySize, (int)smem);
    lstm_kernel<<<dim3(16, 2), 512, smem>>>(Whh_f, Whh_b, out);
}

// round 9
// speedup vs baseline: 1.9009x; 1.0165x over previous
#include <cuda_runtime.h>
#include <math.h>
#include <stdint.h>

#define BB 16
#define LL1 512
#define LL2 512
#define EMB 300
#define AH 256
#define ATTD 250
#define HID 128
#define ATT_IN 812
#define RNN_IN 1280
#define GATES 512  // 4*HID

// ---------------- scratch (device globals; no allocation allowed) ----------------
__device__ float g_xatt[2 * BB * 512 * ATT_IN];   // x1att rows 0..8191, x2att rows 8192..16383
__device__ float g_r[3 * 16384 * 256];            // per head: [16384][256] (ATTD padded)
__device__ float g_scores3[3 * BB * LL1 * LL2];   // [head][b][l][m]
__device__ float g_x2cat3[3 * BB * LL2 * AH];     // [head][b][m][256]
__device__ float g_x1cat[BB * LL1 * RNN_IN];
__device__ float g_gin[LL1 * BB * 1024];          // [l*16+b][dir*512 + gate]
__device__ float g_Wih[1024 * RNN_IN];            // rows 0..511 fwd, 512..1023 bwd
__device__ float g_bih[1024];

// ---------------- concat builders ----------------
__global__ void build_xatt(const float* __restrict__ w1, const float* __restrict__ a10,
                           const float* __restrict__ a11, const float* __restrict__ w2,
                           const float* __restrict__ a20, const float* __restrict__ a21) {
    long idx = (long)blockIdx.x * blockDim.x + threadIdx.x;
    if (idx >= (long)2 * BB * 512 * ATT_IN) return;
    int c = (int)(idx % ATT_IN);
    long row = idx / ATT_IN;
    const float* w = w1; const float* a0 = a10; const float* a1 = a11;
    long r = row;
    if (row >= (long)BB * 512) { w = w2; a0 = a20; a1 = a21; r = row - BB * 512; }
    float v;
    if (c < EMB) v = w[r * EMB + c];
    else if (c < EMB + AH) v = a0[r * AH + (c - EMB)];
    else v = a1[r * AH + (c - EMB - AH)];
    g_xatt[idx] = v;
}

__global__ void build_x1cat_head(const float* __restrict__ a0, const float* __restrict__ a1) {
    int idx = blockIdx.x * blockDim.x + threadIdx.x;
    if (idx >= BB * LL1 * 512) return;
    int c = idx % 512;
    int r = idx / 512;
    float v = (c < 256) ? a0[r * 256 + c] : a1[r * 256 + (c - 256)];
    g_x1cat[(long)r * RNN_IN + c] = v;
}

__global__ void build_x2cat3(const float* __restrict__ a0, const float* __restrict__ a1,
                             const float* __restrict__ a2) {
    long idx = (long)blockIdx.x * blockDim.x + threadIdx.x;
    long per = (long)BB * LL2 * AH;
    if (idx >= 3 * per) return;
    int head = (int)(idx / per);
    long off = idx % per;
    const float* src = (head == 0) ? a0 : (head == 1) ? a1 : a2;
    g_x2cat3[idx] = src[off];
}

__global__ void build_wih(const float* __restrict__ Wf, const float* __restrict__ Wb,
                          const float* __restrict__ bf, const float* __restrict__ bb) {
    int idx = blockIdx.x * blockDim.x + threadIdx.x;
    if (idx < 1024) g_bih[idx] = (idx < 512) ? bf[idx] : bb[idx - 512];
    if (idx >= 1024 * RNN_IN) return;
    int row = idx / RNN_IN;
    int col = idx % RNN_IN;
    g_Wih[idx] = (row < 512) ? Wf[row * RNN_IN + col] : Wb[(row - 512) * RNN_IN + col];
}

// ---------------- bf16 / f32x2 helpers ----------------
__device__ __forceinline__ uint32_t pack_bf16(float lo, float hi) {
    uint32_t r;
    asm("cvt.rn.bf16x2.f32 %0, %1, %2;" : "=r"(r) : "f"(hi), "f"(lo));
    return r;
}

__device__ __forceinline__ void split_bf16(float lo, float hi, uint32_t& big, uint32_t& small) {
    big = pack_bf16(lo, hi);
    float blo = __uint_as_float(big << 16);
    float bhi = __uint_as_float(big & 0xffff0000u);
    small = pack_bf16(lo - blo, hi - bhi);
}

__device__ __forceinline__ void mma_bf16(float* d, const uint32_t* a, const uint32_t* b) {
    asm volatile(
        "mma.sync.aligned.m16n8k16.row.col.f32.bf16.bf16.f32 "
        "{%0,%1,%2,%3}, {%4,%5,%6,%7}, {%8,%9}, {%0,%1,%2,%3};"
        : "+f"(d[0]), "+f"(d[1]), "+f"(d[2]), "+f"(d[3])
        : "r"(a[0]), "r"(a[1]), "r"(a[2]), "r"(a[3]), "r"(b[0]), "r"(b[1]));
}

__device__ __forceinline__ unsigned long long fma2_(unsigned long long a,
                                                   unsigned long long b,
                                                   unsigned long long c) {
    unsigned long long d;
    asm("fma.rn.f32x2 %0, %1, %2, %3;" : "=l"(d) : "l"(a), "l"(b), "l"(c));
    return d;
}

// ---------- 3xBF16 tensor-core GEMM: 128x128 block, 8 warps (2m x 4n) ----------
// Two-level batch: z1 = z & ((1<<zshift)-1), z2 = z >> zshift; X += z1*sX + z2*sX2.
// K-step 16 = one m16n8k16 MMA. Split big/small bf16; acc += As*Bb + Ab*Bs + Ab*Bb.
__global__ void __launch_bounds__(256, 2)
gemm_tc(const float* __restrict__ A, int lda, long sA, long sA2,
        const float* __restrict__ Bm, int ldb, long sB, long sB2, int transB,
        float* __restrict__ C, int ldc, long sC, long sC2,
        int M, int N, int K, int zshift,
        const float* __restrict__ bias,
        const float* __restrict__ vscale, int vzstride, int vstart,
        int doRelu, int permuteOut) {
    extern __shared__ uint32_t smu[];

    int z = blockIdx.z;
    int z1 = z & ((1 << zshift) - 1);
    int z2 = z >> zshift;
    A += z1 * sA + z2 * sA2;
    Bm += z1 * sB + z2 * sB2;
    C += z1 * sC + z2 * sC2;

    int m0 = blockIdx.y * 128;
    int n0 = blockIdx.x * 128;
    int tid = threadIdx.x;
    int wid = tid >> 5;
    int lane = tid & 31;
    int g = lane >> 2;
    int tg = lane & 3;
    int warp_m = wid & 1;
    int warp_n = wid >> 1;

    float acc[4][4][4];
#pragma unroll
    for (int i = 0; i < 4; i++)
#pragma unroll
        for (int j = 0; j < 4; j++)
#pragma unroll
            for (int q = 0; q < 4; q++) acc[i][j][q] = 0.f;

    // ---- A staging ownership: quad q = tid ----
    int a_mt = tid >> 5;
    int a_r = (tid & 31) >> 2;
    int a_c = (tid & 3) * 2;
    int rowa = m0 + a_mt * 16 + a_r;
    const float* aP = A + (long)rowa * lda + a_c;
    long aRow8 = (long)8 * lda;

    // ---- B staging ownership: pairs p = tid, tid+256 ----
    int bN[2], bC[2];
    float nmask[2];
    const float* bP[2];
    long ldbL = ldb;
#pragma unroll
    for (int i = 0; i < 2; i++) {
        int p = tid + 256 * i;
        int l = p & 31;
        bN[i] = n0 + (p >> 5) * 8 + (l >> 2);
        bC[i] = (l & 3) * 2;
        nmask[i] = (bN[i] < N) ? 1.f : 0.f;
        int nc = (bN[i] < N) ? bN[i] : (N - 1);
        bP[i] = transB ? (Bm + (long)nc * ldbL + bC[i])
                       : (Bm + (long)bC[i] * ldbL + nc);
    }
    long bAdv = transB ? 16 : 16 * ldbL;

    float av[8];
    float bv[2][4];

    int fullT = K >> 4;
    int nk = (K + 15) >> 4;

    // ---- prologue: guarded load of tile 0 ----
    {
        int c0 = a_c, c1 = a_c + 1, c2 = a_c + 8, c3 = a_c + 9;
        av[0] = (c0 < K) ? aP[0] : 0.f;
        av[1] = (c1 < K) ? aP[1] : 0.f;
        av[2] = (c0 < K) ? aP[aRow8] : 0.f;
        av[3] = (c1 < K) ? aP[aRow8 + 1] : 0.f;
        av[4] = (c2 < K) ? aP[8] : 0.f;
        av[5] = (c3 < K) ? aP[9] : 0.f;
        av[6] = (c2 < K) ? aP[aRow8 + 8] : 0.f;
        av[7] = (c3 < K) ? aP[aRow8 + 9] : 0.f;
#pragma unroll
        for (int i = 0; i < 2; i++) {
            int c0b = bC[i], c1b = bC[i] + 1, c2b = bC[i] + 8, c3b = bC[i] + 9;
            float v0, v1, v2, v3;
            if (transB) {
                v0 = (c0b < K) ? bP[i][0] : 0.f;
                v1 = (c1b < K) ? bP[i][1] : 0.f;
                v2 = (c2b < K) ? bP[i][8] : 0.f;
                v3 = (c3b < K) ? bP[i][9] : 0.f;
            } else {
                v0 = (c0b < K) ? bP[i][0] : 0.f;
                v1 = (c1b < K) ? bP[i][ldbL] : 0.f;
                v2 = (c2b < K) ? bP[i][8 * ldbL] : 0.f;
                v3 = (c3b < K) ? bP[i][9 * ldbL] : 0.f;
            }
            bv[i][0] = v0 * nmask[i]; bv[i][1] = v1 * nmask[i];
            bv[i][2] = v2 * nmask[i]; bv[i][3] = v3 * nmask[i];
        }
    }

    for (int it = 0; it < nk; it++) {
        uint32_t* buf = smu + (it & 1) * 4096;
        uint32_t* AfB = buf;
        uint32_t* AfS = buf + 1024;
        uint32_t* BfB = buf + 2048;
        uint32_t* BfS = buf + 3072;

        // ---- split + conflict-free wide stores ----
        {
            uint32_t b0, s0, b1, s1, b2, s2, b3, s3;
            split_bf16(av[0], av[1], b0, s0);
            split_bf16(av[2], av[3], b1, s1);
            split_bf16(av[4], av[5], b2, s2);
            split_bf16(av[6], av[7], b3, s3);
            *(uint4*)(AfB + tid * 4) = make_uint4(b0, b1, b2, b3);
            *(uint4*)(AfS + tid * 4) = make_uint4(s0, s1, s2, s3);
        }
#pragma unroll
        for (int i = 0; i < 2; i++) {
            int p = tid + 256 * i;
            uint32_t b0, s0, b1, s1;
            split_bf16(bv[i][0], bv[i][1], b0, s0);
            split_bf16(bv[i][2], bv[i][3], b1, s1);
            *(uint2*)(BfB + p * 2) = make_uint2(b0, b1);
            *(uint2*)(BfS + p * 2) = make_uint2(s0, s1);
        }

        // ---- prefetch next k-tile into regs ----
        if (it + 1 < fullT) {
            aP += 16;
            float2 x0 = *(const float2*)aP;
            float2 x1 = *(const float2*)(aP + aRow8);
            float2 x2 = *(const float2*)(aP + 8);
            float2 x3 = *(const float2*)(aP + aRow8 + 8);
            av[0] = x0.x; av[1] = x0.y; av[2] = x1.x; av[3] = x1.y;
            av[4] = x2.x; av[5] = x2.y; av[6] = x3.x; av[7] = x3.y;
            if (transB) {
#pragma unroll
                for (int i = 0; i < 2; i++) {
                    bP[i] += bAdv;
                    float2 y0 = *(const float2*)bP[i];
                    float2 y1 = *(const float2*)(bP[i] + 8);
                    bv[i][0] = y0.x * nmask[i]; bv[i][1] = y0.y * nmask[i];
                    bv[i][2] = y1.x * nmask[i]; bv[i][3] = y1.y * nmask[i];
                }
            } else {
#pragma unroll
                for (int i = 0; i < 2; i++) {
                    bP[i] += bAdv;
                    bv[i][0] = bP[i][0] * nmask[i];
                    bv[i][1] = bP[i][ldbL] * nmask[i];
                    bv[i][2] = bP[i][8 * ldbL] * nmask[i];
                    bv[i][3] = bP[i][9 * ldbL] * nmask[i];
                }
            }
        } else if (it + 1 < nk) {
            int kb = (it + 1) << 4;
            aP += 16;
            int c0 = kb + a_c, c1 = c0 + 1, c2 = c0 + 8, c3 = c0 + 9;
            av[0] = (c0 < K) ? aP[0] : 0.f;
            av[1] = (c1 < K) ? aP[1] : 0.f;
            av[2] = (c0 < K) ? aP[aRow8] : 0.f;
            av[3] = (c1 < K) ? aP[aRow8 + 1] : 0.f;
            av[4] = (c2 < K) ? aP[8] : 0.f;
            av[5] = (c3 < K) ? aP[9] : 0.f;
            av[6] = (c2 < K) ? aP[aRow8 + 8] : 0.f;
            av[7] = (c3 < K) ? aP[aRow8 + 9] : 0.f;
#pragma unroll
            for (int i = 0; i < 2; i++) {
                bP[i] += bAdv;
                int c0b = kb + bC[i], c1b = c0b + 1, c2b = c0b + 8, c3b = c0b + 9;
                float v0, v1, v2, v3;
                if (transB) {
                    v0 = (c0b < K) ? bP[i][0] : 0.f;
                    v1 = (c1b < K) ? bP[i][1] : 0.f;
                    v2 = (c2b < K) ? bP[i][8] : 0.f;
                    v3 = (c3b < K) ? bP[i][9] : 0.f;
                } else {
                    v0 = (c0b < K) ? bP[i][0] : 0.f;
                    v1 = (c1b < K) ? bP[i][ldbL] : 0.f;
                    v2 = (c2b < K) ? bP[i][8 * ldbL] : 0.f;
                    v3 = (c3b < K) ? bP[i][9 * ldbL] : 0.f;
                }
                bv[i][0] = v0 * nmask[i]; bv[i][1] = v1 * nmask[i];
                bv[i][2] = v2 * nmask[i]; bv[i][3] = v3 * nmask[i];
            }
        }

        __syncthreads();

        // ---- MMA: 16 fragments x 3 (k16 per MMA) ----
        const uint4* aB4 = (const uint4*)(AfB + warp_m * 512 + lane * 4);
        const uint4* aS4 = (const uint4*)(AfS + warp_m * 512 + lane * 4);
        const uint2* bB2 = (const uint2*)(BfB + warp_n * 256 + lane * 2);
        const uint2* bS2 = (const uint2*)(BfS + warp_n * 256 + lane * 2);
        uint32_t afB[4][4], afS[4][4], bfB[4][2], bfS[4][2];
#pragma unroll
        for (int mi = 0; mi < 4; mi++) {
            uint4 vb = aB4[mi * 32];
            uint4 vs = aS4[mi * 32];
            afB[mi][0] = vb.x; afB[mi][1] = vb.y; afB[mi][2] = vb.z; afB[mi][3] = vb.w;
            afS[mi][0] = vs.x; afS[mi][1] = vs.y; afS[mi][2] = vs.z; afS[mi][3] = vs.w;
        }
#pragma unroll
        for (int nj = 0; nj < 4; nj++) {
            uint2 vb = bB2[nj * 32];
            uint2 vs = bS2[nj * 32];
            bfB[nj][0] = vb.x; bfB[nj][1] = vb.y;
            bfS[nj][0] = vs.x; bfS[nj][1] = vs.y;
        }
#pragma unroll
        for (int mi = 0; mi < 4; mi++)
#pragma unroll
            for (int nj = 0; nj < 4; nj++) {
                mma_bf16(acc[mi][nj], afS[mi], bfB[nj]);
                mma_bf16(acc[mi][nj], afB[mi], bfS[nj]);
                mma_bf16(acc[mi][nj], afB[mi], bfB[nj]);
            }
        // no second sync: ping-pong buffer + next iteration's sync protect reuse
    }

    // ---- epilogue ----
    bool applyV = (vscale != nullptr) && (m0 >= vstart);
    const float* vs = vscale + (long)z2 * vzstride;
#pragma unroll
    for (int mi = 0; mi < 4; mi++) {
        int r0 = m0 + warp_m * 64 + mi * 16 + g;
        int r1 = r0 + 8;
        int o0 = permuteOut ? ((r0 & 511) * 16 + (r0 >> 9)) : r0;
        int o1 = permuteOut ? ((r1 & 511) * 16 + (r1 >> 9)) : r1;
        float* c0p = C + (long)o0 * ldc;
        float* c1p = C + (long)o1 * ldc;
#pragma unroll
        for (int nj = 0; nj < 4; nj++) {
            int col = n0 + warp_n * 32 + nj * 8 + 2 * tg;
            if (col >= N) continue;   // N even -> pair-guard safe
            float v0 = acc[mi][nj][0], v1 = acc[mi][nj][1];
            float v2 = acc[mi][nj][2], v3 = acc[mi][nj][3];
            if (bias) {
                float b0 = bias[col], b1 = bias[col + 1];
                v0 += b0; v1 += b1; v2 += b0; v3 += b1;
            }
            if (doRelu) {
                v0 = fmaxf(v0, 0.f); v1 = fmaxf(v1, 0.f);
                v2 = fmaxf(v2, 0.f); v3 = fmaxf(v3, 0.f);
            }
            if (applyV) {
                float s0 = vs[col], s1 = vs[col + 1];
                v0 *= s0; v1 *= s1; v2 *= s0; v3 *= s1;
            }
            *(float2*)(c0p + col) = make_float2(v0, v1);
            *(float2*)(c1p + col) = make_float2(v2, v3);
        }
    }
}

// ---------------- masked softmax over rows of g_scores3 (all 3 heads) ----------------
__global__ void softmax_rows3(const unsigned char* __restrict__ mask) {
    int r = blockIdx.x;          // head*16*512 + b*512 + l
    int b = (r >> 9) & 15;
    float* row = g_scores3 + (long)r * LL2;
    __shared__ float red[256];
    int t = threadIdx.x;

    float v0 = row[t];
    float v1 = row[t + 256];
    if (mask[b * LL2 + t]) v0 = -3.402823466e38f;
    if (mask[b * LL2 + t + 256]) v1 = -3.402823466e38f;

    float mx = fmaxf(v0, v1);
    red[t] = mx;
    __syncthreads();
    for (int s = 128; s > 0; s >>= 1) {
        if (t < s) red[t] = fmaxf(red[t], red[t + s]);
        __syncthreads();
    }
    mx = red[0];
    __syncthreads();

    v0 = __expf(v0 - mx);
    v1 = __expf(v1 - mx);
    red[t] = v0 + v1;
    __syncthreads();
    for (int s = 128; s > 0; s >>= 1) {
        if (t < s) red[t] += red[t + s];
        __syncthreads();
    }
    float inv = 1.f / red[0];
    row[t] = v0 * inv;
    row[t + 256] = v1 * inv;
}

// ---------------- BiLSTM recurrence ----------------
__global__ void __launch_bounds__(512, 1)
lstm_kernel(const float* __restrict__ WhhF, const float* __restrict__ WhhB,
            float* __restrict__ out) {
    extern __shared__ float sm[];
    float4* sW4 = (float4*)sm;              // [8][512] float4 = 64KB
    float* h_sh = sm + 8 * 512 * 4;         // [128]
    float* z_sh = h_sh + 128;               // [512]

    int b = blockIdx.x;
    int dir = blockIdx.y;
    const float* Whh = dir ? WhhB : WhhF;
    int j = threadIdx.x;

    unsigned long long wp[48];
#pragma unroll
    for (int k2 = 0; k2 < 48; k2++)
        wp[k2] = *(const unsigned long long*)&Whh[j * HID + 2 * k2];
#pragma unroll
    for (int k4 = 0; k4 < 8; k4++) {
        const float* ws = Whh + j * HID + 96 + 4 * k4;
        sW4[k4 * 512 + j] = make_float4(ws[0], ws[1], ws[2], ws[3]);
    }
    if (j < HID) h_sh[j] = 0.f;
    float c = 0.f;
    __syncthreads();

    int gofs = dir * 512 + j;
    int l0 = dir ? (LL1 - 1) : 0;
    float gcur = g_gin[((long)l0 * BB + b) * 1024 + gofs];

    for (int s = 0; s < LL1; s++) {
        int l = dir ? (LL1 - 1 - s) : s;
        float gnext = 0.f;
        if (s + 1 < LL1) {
            int ln = dir ? (LL1 - 2 - s) : (s + 1);
            gnext = g_gin[((long)ln * BB + b) * 1024 + gofs];
        }

        unsigned long long acc2;
        {
            uint32_t lo = __float_as_uint(gcur);
            asm("mov.b64 %0, {%1, %2};" : "=l"(acc2) : "r"(lo), "r"(0u));
        }
        const unsigned long long* hp = (const unsigned long long*)h_sh;
#pragma unroll
        for (int k2 = 0; k2 < 48; k2++)
            acc2 = fma2_(hp[k2], wp[k2], acc2);
#pragma unroll
        for (int k4 = 0; k4 < 8; k4++) {
            ulonglong2 w2 = *(const ulonglong2*)&sW4[k4 * 512 + j];
            ulonglong2 h2 = *(const ulonglong2*)&h_sh[96 + 4 * k4];
            acc2 = fma2_(h2.x, w2.x, acc2);
            acc2 = fma2_(h2.y, w2.y, acc2);
        }
        uint32_t ulo, uhi;
        asm("mov.b64 {%0, %1}, %2;" : "=r"(ulo), "=r"(uhi) : "l"(acc2));
        z_sh[j] = __uint_as_float(ulo) + __uint_as_float(uhi);
        __syncthreads();
        if (j < HID) {
            float zi = z_sh[j], zf = z_sh[j + 128], zg = z_sh[j + 256], zo = z_sh[j + 384];
            float ii = 1.f / (1.f + __expf(-zi));
            float ff = 1.f / (1.f + __expf(-zf));
            float ag = fabsf(zg);
            float gg = copysignf(1.f - 2.f / (__expf(2.f * ag) + 1.f), zg);
            float oo = 1.f / (1.f + __expf(-zo));
            c = ff * c + ii * gg;
            float ac = fabsf(c);
            float tc = copysignf(1.f - 2.f / (__expf(2.f * ac) + 1.f), c);
            float h = oo * tc;
            h_sh[j] = h;
            out[((long)b * LL1 + l) * 256 + dir * HID + j] = h;
        }
        gcur = gnext;
        __syncthreads();
    }
}

// ---------------- launcher ----------------
extern "C" void kernel_launch(void* const* d_in, const int* in_sizes, int n_in,
                              void* d_out, int out_size) {
    const float* x1_word = (const float*)d_in[0];
    const float* x1_a0   = (const float*)d_in[1];
    const float* x1_a1   = (const float*)d_in[2];
    const float* x2_word = (const float*)d_in[3];
    const float* x2_a0   = (const float*)d_in[4];
    const float* x2_a1   = (const float*)d_in[5];
    const float* x2_a2   = (const float*)d_in[6];
    const unsigned char* x2_mask = (const unsigned char*)d_in[8];
    const float* W_attn  = (const float*)d_in[9];
    const float* v_attn  = (const float*)d_in[10];
    const float* Wih_f   = (const float*)d_in[11];
    const float* Whh_f   = (const float*)d_in[12];
    const float* b_f     = (const float*)d_in[13];
    const float* Wih_b   = (const float*)d_in[14];
    const float* Whh_b   = (const float*)d_in[15];
    const float* b_b     = (const float*)d_in[16];
    float* out = (float*)d_out;

    float *xatt, *rbuf, *scores3, *x2cat3, *x1cat, *wih, *bih, *ginbuf;
    cudaGetSymbolAddress((void**)&xatt, g_xatt);
    cudaGetSymbolAddress((void**)&rbuf, g_r);
    cudaGetSymbolAddress((void**)&scores3, g_scores3);
    cudaGetSymbolAddress((void**)&x2cat3, g_x2cat3);
    cudaGetSymbolAddress((void**)&x1cat, g_x1cat);
    cudaGetSymbolAddress((void**)&wih, g_Wih);
    cudaGetSymbolAddress((void**)&bih, g_bih);
    cudaGetSymbolAddress((void**)&ginbuf, g_gin);

    const int GEMM_SMEM = 2 * 4096 * 4;  // 32 KB (double-buffered bf16 frag tiles)
    cudaFuncSetAttribute(gemm_tc, cudaFuncAttributeMaxDynamicSharedMemorySize, GEMM_SMEM);

    // concat inputs
    {
        long n1 = (long)2 * BB * 512 * ATT_IN;
        build_xatt<<<(int)((n1 + 255) / 256), 256>>>(x1_word, x1_a0, x1_a1,
                                                     x2_word, x2_a0, x2_a1);
        int n3 = BB * LL1 * 512;
        build_x1cat_head<<<(n3 + 255) / 256, 256>>>(x1_a0, x1_a1);
        long n5 = (long)3 * BB * LL2 * AH;
        build_x2cat3<<<(int)((n5 + 255) / 256), 256>>>(x2_a0, x2_a1, x2_a2);
        int n4 = 1024 * RNN_IN;
        build_wih<<<(n4 + 255) / 256, 256>>>(Wih_f, Wih_b, b_f, b_b);
    }

    const long RH = (long)16384 * 256;     // head stride in rbuf
    const long RB = (long)512 * 256;       // batch stride in rbuf
    const long SH = (long)BB * 512 * 512;  // head stride in scores3
    const long SB = (long)512 * 512;       // batch stride in scores3
    const long XH = (long)BB * 512 * 256;  // head stride in x2cat3

    // r = relu([x1att; x2att] @ Wi^T), batched over 3 heads; v applied to x2 rows
    gemm_tc<<<dim3(2, 128, 3), 256, GEMM_SMEM>>>(
        xatt, ATT_IN, 0, 0,
        W_attn, ATT_IN, 0, (long)ATTD * ATT_IN, 1,
        rbuf, 256, 0, RH,
        16384, ATTD, ATT_IN, 0,
        nullptr, v_attn, ATTD, 8192, 1, 0);

    // scores[h][b] = r1[h][b] @ r2[h][b]^T, all heads+batches in one launch (z=48)
    gemm_tc<<<dim3(4, 4, 48), 256, GEMM_SMEM>>>(
        rbuf, 256, RB, RH,
        rbuf + (long)8192 * 256, 256, RB, RH, 1,
        scores3, 512, SB, SH,
        LL1, LL2, ATTD, 4,
        nullptr, nullptr, 0, 0, 0, 0);

    // masked softmax over all 3*16*512 rows
    softmax_rows3<<<3 * BB * LL1, 256>>>(x2_mask);

    // piece[h][b] = alpha[h][b] @ x2cat3[h][b] -> x1cat cols [512+256h, +256)
    gemm_tc<<<dim3(2, 4, 48), 256, GEMM_SMEM>>>(
        scores3, 512, SB, SH,
        x2cat3, 256, RB, XH, 0,
        x1cat + 512, RNN_IN, (long)512 * RNN_IN, 256,
        LL1, AH, LL2, 4,
        nullptr, nullptr, 0, 0, 0, 0);

    // g_in (both dirs) = x1cat @ [Wih_f; Wih_b]^T + b, rows permuted to [l*16+b]
    gemm_tc<<<dim3(8, 64, 1), 256, GEMM_SMEM>>>(
        x1cat, RNN_IN, 0, 0,
        wih, RNN_IN, 0, 0, 1,
        ginbuf, 1024, 0, 0,
        BB * LL1, 1024, RNN_IN, 0,
        bih, nullptr, 0, 0, 0, 1);

    // BiLSTM
    size_t smem = (size_t)(8 * 512 * 4 + 128 + 512) * sizeof(float);
    cudaFuncSetAttribute(lstm_kernel, cudaFuncAttributeMaxDynamicSharedMemorySize, (int)smem);
    lstm_kernel<<<dim3(16, 2), 512, smem>>>(Whh_f, Whh_b, out);
}

// round 12
// speedup vs baseline: 2.0334x; 1.0697x over previous
#include <cuda_runtime.h>
#include <math.h>
#include <stdint.h>

#define BB 16
#define LL1 512
#define LL2 512
#define EMB 300
#define AH 256
#define ATTD 250
#define HID 128
#define ATT_IN 812
#define RNN_IN 1280
#define GATES 512  // 4*HID

// ---------------- scratch (device globals; no allocation allowed) ----------------
__device__ float g_xatt[2 * BB * 512 * ATT_IN];   // x1att rows 0..8191, x2att rows 8192..16383
__device__ float g_r[3 * 16384 * 256];            // per head: [16384][256] (ATTD padded)
__device__ float g_scores3[3 * BB * LL1 * LL2];   // [head][b][l][m]
__device__ float g_x2cat3[3 * BB * LL2 * AH];     // [head][b][m][256]
__device__ float g_x1cat[BB * LL1 * RNN_IN];
__device__ float g_gin[LL1 * BB * 1024];          // [l*16+b][dir*512 + gate]
__device__ float g_Wih[1024 * RNN_IN];            // rows 0..511 fwd, 512..1023 bwd
__device__ float g_bih[1024];

// ---------------- concat builders ----------------
__global__ void build_xatt(const float* __restrict__ w1, const float* __restrict__ a10,
                           const float* __restrict__ a11, const float* __restrict__ w2,
                           const float* __restrict__ a20, const float* __restrict__ a21) {
    long idx = (long)blockIdx.x * blockDim.x + threadIdx.x;
    if (idx >= (long)2 * BB * 512 * ATT_IN) return;
    int c = (int)(idx % ATT_IN);
    long row = idx / ATT_IN;
    const float* w = w1; const float* a0 = a10; const float* a1 = a11;
    long r = row;
    if (row >= (long)BB * 512) { w = w2; a0 = a20; a1 = a21; r = row - BB * 512; }
    float v;
    if (c < EMB) v = w[r * EMB + c];
    else if (c < EMB + AH) v = a0[r * AH + (c - EMB)];
    else v = a1[r * AH + (c - EMB - AH)];
    g_xatt[idx] = v;
}

__global__ void build_x1cat_head(const float* __restrict__ a0, const float* __restrict__ a1) {
    int idx = blockIdx.x * blockDim.x + threadIdx.x;
    if (idx >= BB * LL1 * 512) return;
    int c = idx % 512;
    int r = idx / 512;
    float v = (c < 256) ? a0[r * 256 + c] : a1[r * 256 + (c - 256)];
    g_x1cat[(long)r * RNN_IN + c] = v;
}

__global__ void build_x2cat3(const float* __restrict__ a0, const float* __restrict__ a1,
                             const float* __restrict__ a2) {
    long idx = (long)blockIdx.x * blockDim.x + threadIdx.x;
    long per = (long)BB * LL2 * AH;
    if (idx >= 3 * per) return;
    int head = (int)(idx / per);
    long off = idx % per;
    const float* src = (head == 0) ? a0 : (head == 1) ? a1 : a2;
    g_x2cat3[idx] = src[off];
}

__global__ void build_wih(const float* __restrict__ Wf, const float* __restrict__ Wb,
                          const float* __restrict__ bf, const float* __restrict__ bb) {
    int idx = blockIdx.x * blockDim.x + threadIdx.x;
    if (idx < 1024) g_bih[idx] = (idx < 512) ? bf[idx] : bb[idx - 512];
    if (idx >= 1024 * RNN_IN) return;
    int row = idx / RNN_IN;
    int col = idx % RNN_IN;
    g_Wih[idx] = (row < 512) ? Wf[row * RNN_IN + col] : Wb[(row - 512) * RNN_IN + col];
}

// ---------------- bf16 / f32x2 helpers ----------------
__device__ __forceinline__ uint32_t pack_bf16(float lo, float hi) {
    uint32_t r;
    asm("cvt.rn.bf16x2.f32 %0, %1, %2;" : "=r"(r) : "f"(hi), "f"(lo));
    return r;
}

__device__ __forceinline__ void split_bf16(float lo, float hi, uint32_t& big, uint32_t& small) {
    big = pack_bf16(lo, hi);
    float blo = __uint_as_float(big << 16);
    float bhi = __uint_as_float(big & 0xffff0000u);
    small = pack_bf16(lo - blo, hi - bhi);
}

__device__ __forceinline__ void mma_bf16(float* d, const uint32_t* a, const uint32_t* b) {
    asm volatile(
        "mma.sync.aligned.m16n8k16.row.col.f32.bf16.bf16.f32 "
        "{%0,%1,%2,%3}, {%4,%5,%6,%7}, {%8,%9}, {%0,%1,%2,%3};"
        : "+f"(d[0]), "+f"(d[1]), "+f"(d[2]), "+f"(d[3])
        : "r"(a[0]), "r"(a[1]), "r"(a[2]), "r"(a[3]), "r"(b[0]), "r"(b[1]));
}

__device__ __forceinline__ unsigned long long fma2_(unsigned long long a,
                                                   unsigned long long b,
                                                   unsigned long long c) {
    unsigned long long d;
    asm("fma.rn.f32x2 %0, %1, %2, %3;" : "=l"(d) : "l"(a), "l"(b), "l"(c));
    return d;
}

__device__ __forceinline__ unsigned long long add2_(unsigned long long a,
                                                   unsigned long long b) {
    unsigned long long d;
    asm("add.rn.f32x2 %0, %1, %2;" : "=l"(d) : "l"(a), "l"(b));
    return d;
}

// ---------- 3xBF16 tensor-core GEMM: 128x128 block, 8 warps (2m x 4n) ----------
// Two-level batch: z1 = z & ((1<<zshift)-1), z2 = z >> zshift; X += z1*sX + z2*sX2.
// K-step 16 = one m16n8k16 MMA. Split big/small bf16; acc += As*Bb + Ab*Bs + Ab*Bb.
__global__ void __launch_bounds__(256, 2)
gemm_tc(const float* __restrict__ A, int lda, long sA, long sA2,
        const float* __restrict__ Bm, int ldb, long sB, long sB2, int transB,
        float* __restrict__ C, int ldc, long sC, long sC2,
        int M, int N, int K, int zshift,
        const float* __restrict__ bias,
        const float* __restrict__ vscale, int vzstride, int vstart,
        int doRelu, int permuteOut) {
    extern __shared__ uint32_t smu[];

    int z = blockIdx.z;
    int z1 = z & ((1 << zshift) - 1);
    int z2 = z >> zshift;
    A += z1 * sA + z2 * sA2;
    Bm += z1 * sB + z2 * sB2;
    C += z1 * sC + z2 * sC2;

    int m0 = blockIdx.y * 128;
    int n0 = blockIdx.x * 128;
    int tid = threadIdx.x;
    int wid = tid >> 5;
    int lane = tid & 31;
    int g = lane >> 2;
    int tg = lane & 3;
    int warp_m = wid & 1;
    int warp_n = wid >> 1;

    float acc[4][4][4];
#pragma unroll
    for (int i = 0; i < 4; i++)
#pragma unroll
        for (int j = 0; j < 4; j++)
#pragma unroll
            for (int q = 0; q < 4; q++) acc[i][j][q] = 0.f;

    // ---- A staging ownership: quad q = tid ----
    int a_mt = tid >> 5;
    int a_r = (tid & 31) >> 2;
    int a_c = (tid & 3) * 2;
    int rowa = m0 + a_mt * 16 + a_r;
    const float* aP = A + (long)rowa * lda + a_c;
    long aRow8 = (long)8 * lda;

    // ---- B staging ownership: pairs p = tid, tid+256 ----
    int bN[2], bC[2];
    float nmask[2];
    const float* bP[2];
    long ldbL = ldb;
#pragma unroll
    for (int i = 0; i < 2; i++) {
        int p = tid + 256 * i;
        int l = p & 31;
        bN[i] = n0 + (p >> 5) * 8 + (l >> 2);
        bC[i] = (l & 3) * 2;
        nmask[i] = (bN[i] < N) ? 1.f : 0.f;
        int nc = (bN[i] < N) ? bN[i] : (N - 1);
        bP[i] = transB ? (Bm + (long)nc * ldbL + bC[i])
                       : (Bm + (long)bC[i] * ldbL + nc);
    }
    long bAdv = transB ? 16 : 16 * ldbL;

    float av[8];
    float bv[2][4];

    int fullT = K >> 4;
    int nk = (K + 15) >> 4;

    // ---- prologue: guarded load of tile 0 ----
    {
        int c0 = a_c, c1 = a_c + 1, c2 = a_c + 8, c3 = a_c + 9;
        av[0] = (c0 < K) ? aP[0] : 0.f;
        av[1] = (c1 < K) ? aP[1] : 0.f;
        av[2] = (c0 < K) ? aP[aRow8] : 0.f;
        av[3] = (c1 < K) ? aP[aRow8 + 1] : 0.f;
        av[4] = (c2 < K) ? aP[8] : 0.f;
        av[5] = (c3 < K) ? aP[9] : 0.f;
        av[6] = (c2 < K) ? aP[aRow8 + 8] : 0.f;
        av[7] = (c3 < K) ? aP[aRow8 + 9] : 0.f;
#pragma unroll
        for (int i = 0; i < 2; i++) {
            int c0b = bC[i], c1b = bC[i] + 1, c2b = bC[i] + 8, c3b = bC[i] + 9;
            float v0, v1, v2, v3;
            if (transB) {
                v0 = (c0b < K) ? bP[i][0] : 0.f;
                v1 = (c1b < K) ? bP[i][1] : 0.f;
                v2 = (c2b < K) ? bP[i][8] : 0.f;
                v3 = (c3b < K) ? bP[i][9] : 0.f;
            } else {
                v0 = (c0b < K) ? bP[i][0] : 0.f;
                v1 = (c1b < K) ? bP[i][ldbL] : 0.f;
                v2 = (c2b < K) ? bP[i][8 * ldbL] : 0.f;
                v3 = (c3b < K) ? bP[i][9 * ldbL] : 0.f;
            }
            bv[i][0] = v0 * nmask[i]; bv[i][1] = v1 * nmask[i];
            bv[i][2] = v2 * nmask[i]; bv[i][3] = v3 * nmask[i];
        }
    }

    for (int it = 0; it < nk; it++) {
        uint32_t* buf = smu + (it & 1) * 4096;
        uint32_t* AfB = buf;
        uint32_t* AfS = buf + 1024;
        uint32_t* BfB = buf + 2048;
        uint32_t* BfS = buf + 3072;

        // ---- split + conflict-free wide stores ----
        {
            uint32_t b0, s0, b1, s1, b2, s2, b3, s3;
            split_bf16(av[0], av[1], b0, s0);
            split_bf16(av[2], av[3], b1, s1);
            split_bf16(av[4], av[5], b2, s2);
            split_bf16(av[6], av[7], b3, s3);
            *(uint4*)(AfB + tid * 4) = make_uint4(b0, b1, b2, b3);
            *(uint4*)(AfS + tid * 4) = make_uint4(s0, s1, s2, s3);
        }
#pragma unroll
        for (int i = 0; i < 2; i++) {
            int p = tid + 256 * i;
            uint32_t b0, s0, b1, s1;
            split_bf16(bv[i][0], bv[i][1], b0, s0);
            split_bf16(bv[i][2], bv[i][3], b1, s1);
            *(uint2*)(BfB + p * 2) = make_uint2(b0, b1);
            *(uint2*)(BfS + p * 2) = make_uint2(s0, s1);
        }

        // ---- prefetch next k-tile into regs ----
        if (it + 1 < fullT) {
            aP += 16;
            float2 x0 = *(const float2*)aP;
            float2 x1 = *(const float2*)(aP + aRow8);
            float2 x2 = *(const float2*)(aP + 8);
            float2 x3 = *(const float2*)(aP + aRow8 + 8);
            av[0] = x0.x; av[1] = x0.y; av[2] = x1.x; av[3] = x1.y;
            av[4] = x2.x; av[5] = x2.y; av[6] = x3.x; av[7] = x3.y;
            if (transB) {
#pragma unroll
                for (int i = 0; i < 2; i++) {
                    bP[i] += bAdv;
                    float2 y0 = *(const float2*)bP[i];
                    float2 y1 = *(const float2*)(bP[i] + 8);
                    bv[i][0] = y0.x * nmask[i]; bv[i][1] = y0.y * nmask[i];
                    bv[i][2] = y1.x * nmask[i]; bv[i][3] = y1.y * nmask[i];
                }
            } else {
#pragma unroll
                for (int i = 0; i < 2; i++) {
                    bP[i] += bAdv;
                    bv[i][0] = bP[i][0] * nmask[i];
                    bv[i][1] = bP[i][ldbL] * nmask[i];
                    bv[i][2] = bP[i][8 * ldbL] * nmask[i];
                    bv[i][3] = bP[i][9 * ldbL] * nmask[i];
                }
            }
        } else if (it + 1 < nk) {
            int kb = (it + 1) << 4;
            aP += 16;
            int c0 = kb + a_c, c1 = c0 + 1, c2 = c0 + 8, c3 = c0 + 9;
            av[0] = (c0 < K) ? aP[0] : 0.f;
            av[1] = (c1 < K) ? aP[1] : 0.f;
            av[2] = (c0 < K) ? aP[aRow8] : 0.f;
            av[3] = (c1 < K) ? aP[aRow8 + 1] : 0.f;
            av[4] = (c2 < K) ? aP[8] : 0.f;
            av[5] = (c3 < K) ? aP[9] : 0.f;
            av[6] = (c2 < K) ? aP[aRow8 + 8] : 0.f;
            av[7] = (c3 < K) ? aP[aRow8 + 9] : 0.f;
#pragma unroll
            for (int i = 0; i < 2; i++) {
                bP[i] += bAdv;
                int c0b = kb + bC[i], c1b = c0b + 1, c2b = c0b + 8, c3b = c0b + 9;
                float v0, v1, v2, v3;
                if (transB) {
                    v0 = (c0b < K) ? bP[i][0] : 0.f;
                    v1 = (c1b < K) ? bP[i][1] : 0.f;
                    v2 = (c2b < K) ? bP[i][8] : 0.f;
                    v3 = (c3b < K) ? bP[i][9] : 0.f;
                } else {
                    v0 = (c0b < K) ? bP[i][0] : 0.f;
                    v1 = (c1b < K) ? bP[i][ldbL] : 0.f;
                    v2 = (c2b < K) ? bP[i][8 * ldbL] : 0.f;
                    v3 = (c3b < K) ? bP[i][9 * ldbL] : 0.f;
                }
                bv[i][0] = v0 * nmask[i]; bv[i][1] = v1 * nmask[i];
                bv[i][2] = v2 * nmask[i]; bv[i][3] = v3 * nmask[i];
            }
        }

        __syncthreads();

        // ---- MMA: 16 fragments x 3 (k16 per MMA) ----
        const uint4* aB4 = (const uint4*)(AfB + warp_m * 512 + lane * 4);
        const uint4* aS4 = (const uint4*)(AfS + warp_m * 512 + lane * 4);
        const uint2* bB2 = (const uint2*)(BfB + warp_n * 256 + lane * 2);
        const uint2* bS2 = (const uint2*)(BfS + warp_n * 256 + lane * 2);
        uint32_t afB[4][4], afS[4][4], bfB[4][2], bfS[4][2];
#pragma unroll
        for (int mi = 0; mi < 4; mi++) {
            uint4 vb = aB4[mi * 32];
            uint4 vs = aS4[mi * 32];
            afB[mi][0] = vb.x; afB[mi][1] = vb.y; afB[mi][2] = vb.z; afB[mi][3] = vb.w;
            afS[mi][0] = vs.x; afS[mi][1] = vs.y; afS[mi][2] = vs.z; afS[mi][3] = vs.w;
        }
#pragma unroll
        for (int nj = 0; nj < 4; nj++) {
            uint2 vb = bB2[nj * 32];
            uint2 vs = bS2[nj * 32];
            bfB[nj][0] = vb.x; bfB[nj][1] = vb.y;
            bfS[nj][0] = vs.x; bfS[nj][1] = vs.y;
        }
#pragma unroll
        for (int mi = 0; mi < 4; mi++)
#pragma unroll
            for (int nj = 0; nj < 4; nj++) {
                mma_bf16(acc[mi][nj], afS[mi], bfB[nj]);
                mma_bf16(acc[mi][nj], afB[mi], bfS[nj]);
                mma_bf16(acc[mi][nj], afB[mi], bfB[nj]);
            }
        // no second sync: ping-pong buffer + next iteration's sync protect reuse
    }

    // ---- epilogue ----
    bool applyV = (vscale != nullptr) && (m0 >= vstart);
    const float* vs = vscale + (long)z2 * vzstride;
#pragma unroll
    for (int mi = 0; mi < 4; mi++) {
        int r0 = m0 + warp_m * 64 + mi * 16 + g;
        int r1 = r0 + 8;
        int o0 = permuteOut ? ((r0 & 511) * 16 + (r0 >> 9)) : r0;
        int o1 = permuteOut ? ((r1 & 511) * 16 + (r1 >> 9)) : r1;
        float* c0p = C + (long)o0 * ldc;
        float* c1p = C + (long)o1 * ldc;
#pragma unroll
        for (int nj = 0; nj < 4; nj++) {
            int col = n0 + warp_n * 32 + nj * 8 + 2 * tg;
            if (col >= N) continue;   // N even -> pair-guard safe
            float v0 = acc[mi][nj][0], v1 = acc[mi][nj][1];
            float v2 = acc[mi][nj][2], v3 = acc[mi][nj][3];
            if (bias) {
                float b0 = bias[col], b1 = bias[col + 1];
                v0 += b0; v1 += b1; v2 += b0; v3 += b1;
            }
            if (doRelu) {
                v0 = fmaxf(v0, 0.f); v1 = fmaxf(v1, 0.f);
                v2 = fmaxf(v2, 0.f); v3 = fmaxf(v3, 0.f);
            }
            if (applyV) {
                float s0 = vs[col], s1 = vs[col + 1];
                v0 *= s0; v1 *= s1; v2 *= s0; v3 *= s1;
            }
            *(float2*)(c0p + col) = make_float2(v0, v1);
            *(float2*)(c1p + col) = make_float2(v2, v3);
        }
    }
}

// ---------------- masked softmax over rows of g_scores3 (shuffle-based) ----------------
__global__ void softmax_rows3(const unsigned char* __restrict__ mask) {
    int r = blockIdx.x;          // head*16*512 + b*512 + l
    int b = (r >> 9) & 15;
    float* row = g_scores3 + (long)r * LL2;
    __shared__ float wred[8];
    int t = threadIdx.x;
    int w = t >> 5;

    float v0 = row[t];
    float v1 = row[t + 256];
    if (mask[b * LL2 + t]) v0 = -3.402823466e38f;
    if (mask[b * LL2 + t + 256]) v1 = -3.402823466e38f;

    float mx = fmaxf(v0, v1);
#pragma unroll
    for (int o = 16; o; o >>= 1) mx = fmaxf(mx, __shfl_xor_sync(0xffffffffu, mx, o));
    if ((t & 31) == 0) wred[w] = mx;
    __syncthreads();
    float mxa = wred[0];
#pragma unroll
    for (int i = 1; i < 8; i++) mxa = fmaxf(mxa, wred[i]);

    v0 = __expf(v0 - mxa);
    v1 = __expf(v1 - mxa);
    float s = v0 + v1;
#pragma unroll
    for (int o = 16; o; o >>= 1) s += __shfl_xor_sync(0xffffffffu, s, o);
    __syncthreads();   // protect wred reuse
    if ((t & 31) == 0) wred[w] = s;
    __syncthreads();
    float sa = 0.f;
#pragma unroll
    for (int i = 0; i < 8; i++) sa += wred[i];
    float inv = 1.f / sa;
    row[t] = v0 * inv;
    row[t + 256] = v1 * inv;
}

// ---------------- BiLSTM recurrence ----------------
// 512 threads; thread j computes z[j] with 4 INDEPENDENT f32x2 accumulator
// chains (breaks the 64-deep serial FMA dependency), applies its own gate
// activation before the barrier; the j<128 tail only combines gates.
__global__ void __launch_bounds__(512, 1)
lstm_kernel(const float* __restrict__ WhhF, const float* __restrict__ WhhB,
            float* __restrict__ out) {
    extern __shared__ float sm[];
    float4* sW4 = (float4*)sm;              // [8][512] float4 = 64KB
    float* h_sh = sm + 8 * 512 * 4;         // [128]
    float* z_sh = h_sh + 128;               // [512] (activated gate values)

    int b = blockIdx.x;
    int dir = blockIdx.y;
    const float* Whh = dir ? WhhB : WhhF;
    int j = threadIdx.x;
    int gate = j >> 7;                      // 0:i 1:f 2:g 3:o (warp-uniform)

    unsigned long long wp[48];
#pragma unroll
    for (int k2 = 0; k2 < 48; k2++)
        wp[k2] = *(const unsigned long long*)&Whh[j * HID + 2 * k2];
#pragma unroll
    for (int k4 = 0; k4 < 8; k4++) {
        const float* ws = Whh + j * HID + 96 + 4 * k4;
        sW4[k4 * 512 + j] = make_float4(ws[0], ws[1], ws[2], ws[3]);
    }
    if (j < HID) h_sh[j] = 0.f;
    float c = 0.f;
    __syncthreads();

    int gofs = dir * 512 + j;
    int l0 = dir ? (LL1 - 1) : 0;
    float gcur = g_gin[((long)l0 * BB + b) * 1024 + gofs];

    for (int s = 0; s < LL1; s++) {
        int l = dir ? (LL1 - 1 - s) : s;
        float gnext = 0.f;
        if (s + 1 < LL1) {
            int ln = dir ? (LL1 - 2 - s) : (s + 1);
            gnext = g_gin[((long)ln * BB + b) * 1024 + gofs];
        }

        // ---- 4 independent accumulation chains ----
        unsigned long long a0, a1, a2, a3;
        {
            uint32_t lo = __float_as_uint(gcur);
            asm("mov.b64 %0, {%1, %2};" : "=l"(a0) : "r"(lo), "r"(0u));
            asm("mov.b64 %0, {%1, %2};" : "=l"(a1) : "r"(0u), "r"(0u));
            a2 = a1; a3 = a1;
        }
        const unsigned long long* hp = (const unsigned long long*)h_sh;
#pragma unroll
        for (int k2 = 0; k2 < 12; k2++) {
            a0 = fma2_(hp[k2], wp[k2], a0);
            a1 = fma2_(hp[12 + k2], wp[12 + k2], a1);
            a2 = fma2_(hp[24 + k2], wp[24 + k2], a2);
            a3 = fma2_(hp[36 + k2], wp[36 + k2], a3);
        }
#pragma unroll
        for (int k4 = 0; k4 < 8; k4 += 2) {
            ulonglong2 w0 = *(const ulonglong2*)&sW4[k4 * 512 + j];
            ulonglong2 h0 = *(const ulonglong2*)&h_sh[96 + 4 * k4];
            ulonglong2 w1 = *(const ulonglong2*)&sW4[(k4 + 1) * 512 + j];
            ulonglong2 h1 = *(const ulonglong2*)&h_sh[96 + 4 * (k4 + 1)];
            a0 = fma2_(h0.x, w0.x, a0);
            a1 = fma2_(h0.y, w0.y, a1);
            a2 = fma2_(h1.x, w1.x, a2);
            a3 = fma2_(h1.y, w1.y, a3);
        }
        unsigned long long at = add2_(add2_(a0, a1), add2_(a2, a3));
        uint32_t ulo, uhi;
        asm("mov.b64 {%0, %1}, %2;" : "=r"(ulo), "=r"(uhi) : "l"(at));
        float zv = __uint_as_float(ulo) + __uint_as_float(uhi);

        // ---- distributed activation (warp-uniform branch) ----
        float act;
        if (gate == 2) {
            float az = fabsf(zv);
            act = copysignf(1.f - 2.f / (__expf(2.f * az) + 1.f), zv);   // tanh
        } else {
            act = 1.f / (1.f + __expf(-zv));                              // sigmoid
        }
        z_sh[j] = act;
        __syncthreads();

        // ---- short tail: combine gates ----
        if (j < HID) {
            float ii = z_sh[j], ff = z_sh[j + 128], gg = z_sh[j + 256], oo = z_sh[j + 384];
            c = ff * c + ii * gg;
            float ac = fabsf(c);
            float tc = copysignf(1.f - 2.f / (__expf(2.f * ac) + 1.f), c);
            float h = oo * tc;
            h_sh[j] = h;
            out[((long)b * LL1 + l) * 256 + dir * HID + j] = h;
        }
        gcur = gnext;
        __syncthreads();
    }
}

// ---------------- launcher ----------------
extern "C" void kernel_launch(void* const* d_in, const int* in_sizes, int n_in,
                              void* d_out, int out_size) {
    const float* x1_word = (const float*)d_in[0];
    const float* x1_a0   = (const float*)d_in[1];
    const float* x1_a1   = (const float*)d_in[2];
    const float* x2_word = (const float*)d_in[3];
    const float* x2_a0   = (const float*)d_in[4];
    const float* x2_a1   = (const float*)d_in[5];
    const float* x2_a2   = (const float*)d_in[6];
    const unsigned char* x2_mask = (const unsigned char*)d_in[8];
    const float* W_attn  = (const float*)d_in[9];
    const float* v_attn  = (const float*)d_in[10];
    const float* Wih_f   = (const float*)d_in[11];
    const float* Whh_f   = (const float*)d_in[12];
    const float* b_f     = (const float*)d_in[13];
    const float* Wih_b   = (const float*)d_in[14];
    const float* Whh_b   = (const float*)d_in[15];
    const float* b_b     = (const float*)d_in[16];
    float* out = (float*)d_out;

    float *xatt, *rbuf, *scores3, *x2cat3, *x1cat, *wih, *bih, *ginbuf;
    cudaGetSymbolAddress((void**)&xatt, g_xatt);
    cudaGetSymbolAddress((void**)&rbuf, g_r);
    cudaGetSymbolAddress((void**)&scores3, g_scores3);
    cudaGetSymbolAddress((void**)&x2cat3, g_x2cat3);
    cudaGetSymbolAddress((void**)&x1cat, g_x1cat);
    cudaGetSymbolAddress((void**)&wih, g_Wih);
    cudaGetSymbolAddress((void**)&bih, g_bih);
    cudaGetSymbolAddress((void**)&ginbuf, g_gin);

    const int GEMM_SMEM = 2 * 4096 * 4;  // 32 KB (double-buffered bf16 frag tiles)
    cudaFuncSetAttribute(gemm_tc, cudaFuncAttributeMaxDynamicSharedMemorySize, GEMM_SMEM);

    // concat inputs
    {
        long n1 = (long)2 * BB * 512 * ATT_IN;
        build_xatt<<<(int)((n1 + 255) / 256), 256>>>(x1_word, x1_a0, x1_a1,
                                                     x2_word, x2_a0, x2_a1);
        int n3 = BB * LL1 * 512;
        build_x1cat_head<<<(n3 + 255) / 256, 256>>>(x1_a0, x1_a1);
        long n5 = (long)3 * BB * LL2 * AH;
        build_x2cat3<<<(int)((n5 + 255) / 256), 256>>>(x2_a0, x2_a1, x2_a2);
        int n4 = 1024 * RNN_IN;
        build_wih<<<(n4 + 255) / 256, 256>>>(Wih_f, Wih_b, b_f, b_b);
    }

    const long RH = (long)16384 * 256;     // head stride in rbuf
    const long RB = (long)512 * 256;       // batch stride in rbuf
    const long SH = (long)BB * 512 * 512;  // head stride in scores3
    const long SB = (long)512 * 512;       // batch stride in scores3
    const long XH = (long)BB * 512 * 256;  // head stride in x2cat3

    // r = relu([x1att; x2att] @ Wi^T), batched over 3 heads; v applied to x2 rows
    gemm_tc<<<dim3(2, 128, 3), 256, GEMM_SMEM>>>(
        xatt, ATT_IN, 0, 0,
        W_attn, ATT_IN, 0, (long)ATTD * ATT_IN, 1,
        rbuf, 256, 0, RH,
        16384, ATTD, ATT_IN, 0,
        nullptr, v_attn, ATTD, 8192, 1, 0);

    // scores[h][b] = r1[h][b] @ r2[h][b]^T, all heads+batches in one launch (z=48)
    gemm_tc<<<dim3(4, 4, 48), 256, GEMM_SMEM>>>(
        rbuf, 256, RB, RH,
        rbuf + (long)8192 * 256, 256, RB, RH, 1,
        scores3, 512, SB, SH,
        LL1, LL2, ATTD, 4,
        nullptr, nullptr, 0, 0, 0, 0);

    // masked softmax over all 3*16*512 rows
    softmax_rows3<<<3 * BB * LL1, 256>>>(x2_mask);

    // piece[h][b] = alpha[h][b] @ x2cat3[h][b] -> x1cat cols [512+256h, +256)
    gemm_tc<<<dim3(2, 4, 48), 256, GEMM_SMEM>>>(
        scores3, 512, SB, SH,
        x2cat3, 256, RB, XH, 0,
        x1cat + 512, RNN_IN, (long)512 * RNN_IN, 256,
        LL1, AH, LL2, 4,
        nullptr, nullptr, 0, 0, 0, 0);

    // g_in (both dirs) = x1cat @ [Wih_f; Wih_b]^T + b, rows permuted to [l*16+b]
    gemm_tc<<<dim3(8, 64, 1), 256, GEMM_SMEM>>>(
        x1cat, RNN_IN, 0, 0,
        wih, RNN_IN, 0, 0, 1,
        ginbuf, 1024, 0, 0,
        BB * LL1, 1024, RNN_IN, 0,
        bih, nullptr, 0, 0, 0, 1);

    // BiLSTM
    size_t smem = (size_t)(8 * 512 * 4 + 128 + 512) * sizeof(float);
    cudaFuncSetAttribute(lstm_kernel, cudaFuncAttributeMaxDynamicSharedMemorySize, (int)smem);
    lstm_kernel<<<dim3(16, 2), 512, smem>>>(Whh_f, Whh_b, out);
}